// round 1
// baseline (speedup 1.0000x reference)
#include <cuda_runtime.h>

#define NN   100000
#define FEAT 128
#define CLS  40

// ---- scratch (static device globals; no allocation allowed) ----
__device__ float g_deg[NN];
__device__ float g_dinv[NN];
__device__ float g_H[(size_t)NN * FEAT];    // GEMM output (messages source)
__device__ float g_AGG[(size_t)NN * FEAT];  // aggregation buffer
__device__ float g_H2[(size_t)NN * CLS];    // last-layer GEMM output
__device__ int   g_is64;                    // edge_index dtype flag

// ------------------------------------------------------------------
// degree / dinv
// ------------------------------------------------------------------
__global__ void k_zero_deg(const void* ei, int n) {
    int i = blockIdx.x * blockDim.x + threadIdx.x;
    if (i < n) g_deg[i] = 0.f;
    if (i == 0) {
        // int64 vs int32 detection: if data is int32, a 64-bit word holds two
        // random values in [0,N) -> value >= 2^32 almost surely. Check 2 words.
        const unsigned long long* p = (const unsigned long long*)ei;
        g_is64 = (p[0] < (unsigned long long)n && p[1] < (unsigned long long)n) ? 1 : 0;
    }
}

__global__ void k_count(const void* ei, int E) {
    int e = blockIdx.x * blockDim.x + threadIdx.x;
    if (e >= E) return;
    int dst;
    if (g_is64) dst = (int)((const long long*)ei)[E + e];
    else        dst = ((const int*)ei)[E + e];
    atomicAdd(&g_deg[dst], 1.f);
}

__global__ void k_dinv(int n) {
    int i = blockIdx.x * blockDim.x + threadIdx.x;
    if (i < n) g_dinv[i] = rsqrtf(g_deg[i] + 1.f);
}

// ------------------------------------------------------------------
// GEMM (K=128, Nout=128): H = act(A) @ W ; AGG = H * dinv^2 + b
// 64 rows/block, 256 threads, thread tile 4x8
// ------------------------------------------------------------------
template <bool RELU>
__global__ __launch_bounds__(256)
void k_gemm128(const float* __restrict__ A, const float* __restrict__ W,
               const float* __restrict__ b, float* __restrict__ H,
               float* __restrict__ AGG, int n) {
    __shared__ float Ws[32][128];
    __shared__ float As[64][33];
    const int tid = threadIdx.x;
    const int tx = tid & 15;     // col group: cols tx*8 .. tx*8+7
    const int ty = tid >> 4;     // row group: rows ty*4 .. ty*4+3
    const int row0 = blockIdx.x * 64;

    float acc[4][8];
#pragma unroll
    for (int i = 0; i < 4; i++)
#pragma unroll
        for (int j = 0; j < 8; j++) acc[i][j] = 0.f;

    for (int k0 = 0; k0 < 128; k0 += 32) {
        // load W chunk [32 x 128]
#pragma unroll
        for (int l = 0; l < 4; l++) {
            int idx = tid + l * 256;       // float4 index of 1024
            int kk = idx >> 5, cc = idx & 31;
            float4 w = *(const float4*)(W + (size_t)(k0 + kk) * 128 + cc * 4);
            *(float4*)&Ws[kk][cc * 4] = w;
        }
        // load A chunk [64 rows x 32 k]
#pragma unroll
        for (int l = 0; l < 2; l++) {
            int idx = tid + l * 256;       // float4 index of 512
            int r = idx >> 3, c = idx & 7;
            int gr = row0 + r;
            float4 a = make_float4(0.f, 0.f, 0.f, 0.f);
            if (gr < n) a = *(const float4*)(A + (size_t)gr * 128 + k0 + c * 4);
            if (RELU) {
                a.x = fmaxf(a.x, 0.f); a.y = fmaxf(a.y, 0.f);
                a.z = fmaxf(a.z, 0.f); a.w = fmaxf(a.w, 0.f);
            }
            As[r][c * 4 + 0] = a.x; As[r][c * 4 + 1] = a.y;
            As[r][c * 4 + 2] = a.z; As[r][c * 4 + 3] = a.w;
        }
        __syncthreads();
#pragma unroll
        for (int k = 0; k < 32; k++) {
            float4 w0 = *(const float4*)&Ws[k][tx * 8];
            float4 w1 = *(const float4*)&Ws[k][tx * 8 + 4];
            float av[4];
#pragma unroll
            for (int i = 0; i < 4; i++) av[i] = As[ty * 4 + i][k];
#pragma unroll
            for (int i = 0; i < 4; i++) {
                acc[i][0] += av[i] * w0.x; acc[i][1] += av[i] * w0.y;
                acc[i][2] += av[i] * w0.z; acc[i][3] += av[i] * w0.w;
                acc[i][4] += av[i] * w1.x; acc[i][5] += av[i] * w1.y;
                acc[i][6] += av[i] * w1.z; acc[i][7] += av[i] * w1.w;
            }
        }
        __syncthreads();
    }

    float4 bv0 = *(const float4*)(b + tx * 8);
    float4 bv1 = *(const float4*)(b + tx * 8 + 4);
#pragma unroll
    for (int i = 0; i < 4; i++) {
        int gr = row0 + ty * 4 + i;
        if (gr >= n) continue;
        float di = g_dinv[gr];
        float dd = di * di;
        float4 h0 = make_float4(acc[i][0], acc[i][1], acc[i][2], acc[i][3]);
        float4 h1 = make_float4(acc[i][4], acc[i][5], acc[i][6], acc[i][7]);
        *(float4*)(H + (size_t)gr * 128 + tx * 8)     = h0;
        *(float4*)(H + (size_t)gr * 128 + tx * 8 + 4) = h1;
        float4 g0 = make_float4(h0.x * dd + bv0.x, h0.y * dd + bv0.y,
                                h0.z * dd + bv0.z, h0.w * dd + bv0.w);
        float4 g1 = make_float4(h1.x * dd + bv1.x, h1.y * dd + bv1.y,
                                h1.z * dd + bv1.z, h1.w * dd + bv1.w);
        *(float4*)(AGG + (size_t)gr * 128 + tx * 8)     = g0;
        *(float4*)(AGG + (size_t)gr * 128 + tx * 8 + 4) = g1;
    }
}

// ------------------------------------------------------------------
// GEMM (K=128, Nout=40): H2 = relu(A) @ W2 ; OUT = H2 * dinv^2 + b2
// 64 rows/block, 256 threads, thread tile 2x5
// ------------------------------------------------------------------
template <bool RELU>
__global__ __launch_bounds__(256)
void k_gemm40(const float* __restrict__ A, const float* __restrict__ W,
              const float* __restrict__ b, float* __restrict__ H2,
              float* __restrict__ OUT, int n) {
    __shared__ float Ws[128][44];
    __shared__ float As[64][33];
    const int tid = threadIdx.x;
    const int tx = tid & 7;      // col group: cols tx*5 .. tx*5+4
    const int ty = tid >> 3;     // row group: rows ty*2 .. ty*2+1
    const int row0 = blockIdx.x * 64;

    for (int idx = tid; idx < 128 * 40; idx += 256) {
        int kk = idx / 40, nn = idx % 40;
        Ws[kk][nn] = W[idx];
    }

    float acc[2][5];
#pragma unroll
    for (int i = 0; i < 2; i++)
#pragma unroll
        for (int j = 0; j < 5; j++) acc[i][j] = 0.f;

    for (int k0 = 0; k0 < 128; k0 += 32) {
#pragma unroll
        for (int l = 0; l < 2; l++) {
            int idx = tid + l * 256;
            int r = idx >> 3, c = idx & 7;
            int gr = row0 + r;
            float4 a = make_float4(0.f, 0.f, 0.f, 0.f);
            if (gr < n) a = *(const float4*)(A + (size_t)gr * 128 + k0 + c * 4);
            if (RELU) {
                a.x = fmaxf(a.x, 0.f); a.y = fmaxf(a.y, 0.f);
                a.z = fmaxf(a.z, 0.f); a.w = fmaxf(a.w, 0.f);
            }
            As[r][c * 4 + 0] = a.x; As[r][c * 4 + 1] = a.y;
            As[r][c * 4 + 2] = a.z; As[r][c * 4 + 3] = a.w;
        }
        __syncthreads();
#pragma unroll
        for (int k = 0; k < 32; k++) {
            float a0 = As[ty * 2 + 0][k];
            float a1 = As[ty * 2 + 1][k];
            float wv[5];
#pragma unroll
            for (int j = 0; j < 5; j++) wv[j] = Ws[k0 + k][tx * 5 + j];
#pragma unroll
            for (int j = 0; j < 5; j++) {
                acc[0][j] += a0 * wv[j];
                acc[1][j] += a1 * wv[j];
            }
        }
        __syncthreads();
    }

#pragma unroll
    for (int i = 0; i < 2; i++) {
        int gr = row0 + ty * 2 + i;
        if (gr >= n) continue;
        float di = g_dinv[gr];
        float dd = di * di;
#pragma unroll
        for (int j = 0; j < 5; j++) {
            int c = tx * 5 + j;
            float h = acc[i][j];
            H2[(size_t)gr * 40 + c]  = h;
            OUT[(size_t)gr * 40 + c] = h * dd + b[c];
        }
    }
}

// ------------------------------------------------------------------
// edge scatter: AGG[dst] += dinv[src]*dinv[dst] * H[src]   (one warp/edge)
// ------------------------------------------------------------------
__global__ void k_scatter128(const void* __restrict__ ei,
                             const float* __restrict__ h,
                             float* __restrict__ agg, int E) {
    int w = (blockIdx.x * blockDim.x + threadIdx.x) >> 5;
    if (w >= E) return;
    int lane = threadIdx.x & 31;
    int s, d;
    if (g_is64) {
        const long long* p = (const long long*)ei;
        s = (int)p[w]; d = (int)p[E + w];
    } else {
        const int* p = (const int*)ei;
        s = p[w]; d = p[E + w];
    }
    float nrm = g_dinv[s] * g_dinv[d];
    float4 v = *(const float4*)(h + (size_t)s * 128 + lane * 4);
    float* o = agg + (size_t)d * 128 + lane * 4;
    atomicAdd(o + 0, v.x * nrm);
    atomicAdd(o + 1, v.y * nrm);
    atomicAdd(o + 2, v.z * nrm);
    atomicAdd(o + 3, v.w * nrm);
}

__global__ void k_scatter40(const void* __restrict__ ei,
                            const float* __restrict__ h,
                            float* __restrict__ out, int E) {
    int w = (blockIdx.x * blockDim.x + threadIdx.x) >> 5;
    if (w >= E) return;
    int lane = threadIdx.x & 31;
    if (lane >= 20) return;
    int s, d;
    if (g_is64) {
        const long long* p = (const long long*)ei;
        s = (int)p[w]; d = (int)p[E + w];
    } else {
        const int* p = (const int*)ei;
        s = p[w]; d = p[E + w];
    }
    float nrm = g_dinv[s] * g_dinv[d];
    float2 v = *(const float2*)(h + (size_t)s * 40 + lane * 2);
    float* o = out + (size_t)d * 40 + lane * 2;
    atomicAdd(o + 0, v.x * nrm);
    atomicAdd(o + 1, v.y * nrm);
}

// ------------------------------------------------------------------
extern "C" void kernel_launch(void* const* d_in, const int* in_sizes, int n_in,
                              void* d_out, int out_size) {
    const float* x  = (const float*)d_in[0];
    const float* W0 = (const float*)d_in[1];
    const float* b0 = (const float*)d_in[2];
    const float* W1 = (const float*)d_in[3];
    const float* b1 = (const float*)d_in[4];
    const float* W2 = (const float*)d_in[5];
    const float* b2 = (const float*)d_in[6];
    const void*  ei = d_in[7];
    int n = in_sizes[0] / FEAT;
    int E = in_sizes[7] / 2;
    float* out = (float*)d_out;

    float *pH, *pAGG, *pH2;
    cudaGetSymbolAddress((void**)&pH,   g_H);
    cudaGetSymbolAddress((void**)&pAGG, g_AGG);
    cudaGetSymbolAddress((void**)&pH2,  g_H2);

    const int tb = 256;
    int nblk = (n + tb - 1) / tb;
    int eblk = (E + tb - 1) / tb;
    int gblk = (n + 63) / 64;
    int sblk = (int)(((long long)E * 32 + tb - 1) / tb);

    k_zero_deg<<<nblk, tb>>>(ei, n);
    k_count<<<eblk, tb>>>(ei, E);
    k_dinv<<<nblk, tb>>>(n);

    // layer 0
    k_gemm128<false><<<gblk, 256>>>(x, W0, b0, pH, pAGG, n);
    k_scatter128<<<sblk, tb>>>(ei, pH, pAGG, E);
    // layer 1 (ReLU fused into A-load; in-place over AGG is safe: each block
    // reads only the rows it later writes)
    k_gemm128<true><<<gblk, 256>>>(pAGG, W1, b1, pH, pAGG, n);
    k_scatter128<<<sblk, tb>>>(ei, pH, pAGG, E);
    // layer 2
    k_gemm40<true><<<gblk, 256>>>(pAGG, W2, b2, pH2, out, n);
    k_scatter40<<<sblk, tb>>>(ei, pH2, out, E);
}

// round 2
// speedup vs baseline: 2.6263x; 2.6263x over previous
#include <cuda_runtime.h>

#define NN    100000
#define FEAT  128
#define CLS   40
#define EMAX  1600000

// ---- scratch (static device globals; no allocation allowed) ----
__device__ int   g_degi[NN];
__device__ float g_dinv[NN];
__device__ float g_H[(size_t)NN * FEAT];    // GEMM output (messages source)
__device__ float g_AGG[(size_t)NN * FEAT];  // aggregation buffer
__device__ float g_H2[(size_t)NN * CLS];    // last-layer GEMM output
__device__ int   g_is64;                    // edge_index dtype flag
__device__ int   g_rowptr[NN + 1];
__device__ int   g_cursor[NN];
__device__ int   g_csr[EMAX];               // src ids grouped by dst
__device__ int   g_bsum[128];
__device__ int   g_boff[128];

// ------------------------------------------------------------------
// degree / dinv / CSR build
// ------------------------------------------------------------------
__global__ void k_zero_deg(const void* ei, int n) {
    int i = blockIdx.x * blockDim.x + threadIdx.x;
    if (i < n) g_degi[i] = 0;
    if (i == 0) {
        // int64 vs int32 detection: int32 data viewed as u64 words holds two
        // random values in [0,N) -> word >= 2^32 almost surely. Check 2 words.
        const unsigned long long* p = (const unsigned long long*)ei;
        g_is64 = (p[0] < (unsigned long long)n && p[1] < (unsigned long long)n) ? 1 : 0;
    }
}

__global__ void k_count(const void* ei, int E) {
    int e = blockIdx.x * blockDim.x + threadIdx.x;
    if (e >= E) return;
    int dst;
    if (g_is64) dst = (int)((const long long*)ei)[E + e];
    else        dst = ((const int*)ei)[E + e];
    atomicAdd(&g_degi[dst], 1);
}

__global__ void k_dinv(int n) {
    int i = blockIdx.x * blockDim.x + threadIdx.x;
    if (i < n) g_dinv[i] = rsqrtf((float)g_degi[i] + 1.f);
}

// exclusive scan of g_degi -> g_rowptr, 3 phases
__global__ void k_scanA(int n) {
    __shared__ int s[1024];
    int i = blockIdx.x * 1024 + threadIdx.x;
    int v = (i < n) ? g_degi[i] : 0;
    s[threadIdx.x] = v;
    __syncthreads();
#pragma unroll
    for (int off = 1; off < 1024; off <<= 1) {
        int x = (threadIdx.x >= off) ? s[threadIdx.x - off] : 0;
        __syncthreads();
        s[threadIdx.x] += x;
        __syncthreads();
    }
    if (i < n) g_rowptr[i] = s[threadIdx.x] - v;      // exclusive within block
    if (threadIdx.x == 1023) g_bsum[blockIdx.x] = s[1023];
}

__global__ void k_scanB(int nb) {
    if (threadIdx.x == 0) {
        int acc = 0;
        for (int b = 0; b < nb; b++) { int t = g_bsum[b]; g_boff[b] = acc; acc += t; }
    }
}

__global__ void k_scanC(int n, int E) {
    int i = blockIdx.x * 1024 + threadIdx.x;
    if (i < n) {
        int r = g_rowptr[i] + g_boff[blockIdx.x];
        g_rowptr[i] = r;
        g_cursor[i] = r;
    }
    if (i == 0) g_rowptr[n] = E;
}

__global__ void k_fill(const void* ei, int E) {
    int e = blockIdx.x * blockDim.x + threadIdx.x;
    if (e >= E) return;
    int s, d;
    if (g_is64) {
        const long long* p = (const long long*)ei;
        s = (int)p[e]; d = (int)p[E + e];
    } else {
        const int* p = (const int*)ei;
        s = p[e]; d = p[E + e];
    }
    int pos = atomicAdd(&g_cursor[d], 1);
    g_csr[pos] = s;
}

// ------------------------------------------------------------------
// GEMM (K=128, Nout=128): H = act(A) @ W ; AGG = H * dinv^2 + b
// ------------------------------------------------------------------
template <bool RELU>
__global__ __launch_bounds__(256)
void k_gemm128(const float* __restrict__ A, const float* __restrict__ W,
               const float* __restrict__ b, float* __restrict__ H,
               float* __restrict__ AGG, int n) {
    __shared__ float Ws[32][128];
    __shared__ float As[64][33];
    const int tid = threadIdx.x;
    const int tx = tid & 15;
    const int ty = tid >> 4;
    const int row0 = blockIdx.x * 64;

    float acc[4][8];
#pragma unroll
    for (int i = 0; i < 4; i++)
#pragma unroll
        for (int j = 0; j < 8; j++) acc[i][j] = 0.f;

    for (int k0 = 0; k0 < 128; k0 += 32) {
#pragma unroll
        for (int l = 0; l < 4; l++) {
            int idx = tid + l * 256;
            int kk = idx >> 5, cc = idx & 31;
            float4 w = *(const float4*)(W + (size_t)(k0 + kk) * 128 + cc * 4);
            *(float4*)&Ws[kk][cc * 4] = w;
        }
#pragma unroll
        for (int l = 0; l < 2; l++) {
            int idx = tid + l * 256;
            int r = idx >> 3, c = idx & 7;
            int gr = row0 + r;
            float4 a = make_float4(0.f, 0.f, 0.f, 0.f);
            if (gr < n) a = *(const float4*)(A + (size_t)gr * 128 + k0 + c * 4);
            if (RELU) {
                a.x = fmaxf(a.x, 0.f); a.y = fmaxf(a.y, 0.f);
                a.z = fmaxf(a.z, 0.f); a.w = fmaxf(a.w, 0.f);
            }
            As[r][c * 4 + 0] = a.x; As[r][c * 4 + 1] = a.y;
            As[r][c * 4 + 2] = a.z; As[r][c * 4 + 3] = a.w;
        }
        __syncthreads();
#pragma unroll
        for (int k = 0; k < 32; k++) {
            float4 w0 = *(const float4*)&Ws[k][tx * 8];
            float4 w1 = *(const float4*)&Ws[k][tx * 8 + 4];
            float av[4];
#pragma unroll
            for (int i = 0; i < 4; i++) av[i] = As[ty * 4 + i][k];
#pragma unroll
            for (int i = 0; i < 4; i++) {
                acc[i][0] += av[i] * w0.x; acc[i][1] += av[i] * w0.y;
                acc[i][2] += av[i] * w0.z; acc[i][3] += av[i] * w0.w;
                acc[i][4] += av[i] * w1.x; acc[i][5] += av[i] * w1.y;
                acc[i][6] += av[i] * w1.z; acc[i][7] += av[i] * w1.w;
            }
        }
        __syncthreads();
    }

    float4 bv0 = *(const float4*)(b + tx * 8);
    float4 bv1 = *(const float4*)(b + tx * 8 + 4);
#pragma unroll
    for (int i = 0; i < 4; i++) {
        int gr = row0 + ty * 4 + i;
        if (gr >= n) continue;
        float di = g_dinv[gr];
        float dd = di * di;
        float4 h0 = make_float4(acc[i][0], acc[i][1], acc[i][2], acc[i][3]);
        float4 h1 = make_float4(acc[i][4], acc[i][5], acc[i][6], acc[i][7]);
        *(float4*)(H + (size_t)gr * 128 + tx * 8)     = h0;
        *(float4*)(H + (size_t)gr * 128 + tx * 8 + 4) = h1;
        float4 g0 = make_float4(h0.x * dd + bv0.x, h0.y * dd + bv0.y,
                                h0.z * dd + bv0.z, h0.w * dd + bv0.w);
        float4 g1 = make_float4(h1.x * dd + bv1.x, h1.y * dd + bv1.y,
                                h1.z * dd + bv1.z, h1.w * dd + bv1.w);
        *(float4*)(AGG + (size_t)gr * 128 + tx * 8)     = g0;
        *(float4*)(AGG + (size_t)gr * 128 + tx * 8 + 4) = g1;
    }
}

// ------------------------------------------------------------------
// GEMM (K=128, Nout=40)
// ------------------------------------------------------------------
template <bool RELU>
__global__ __launch_bounds__(256)
void k_gemm40(const float* __restrict__ A, const float* __restrict__ W,
              const float* __restrict__ b, float* __restrict__ H2,
              float* __restrict__ OUT, int n) {
    __shared__ float Ws[128][44];
    __shared__ float As[64][33];
    const int tid = threadIdx.x;
    const int tx = tid & 7;
    const int ty = tid >> 3;
    const int row0 = blockIdx.x * 64;

    for (int idx = tid; idx < 128 * 40; idx += 256) {
        int kk = idx / 40, nn = idx % 40;
        Ws[kk][nn] = W[idx];
    }

    float acc[2][5];
#pragma unroll
    for (int i = 0; i < 2; i++)
#pragma unroll
        for (int j = 0; j < 5; j++) acc[i][j] = 0.f;

    for (int k0 = 0; k0 < 128; k0 += 32) {
#pragma unroll
        for (int l = 0; l < 2; l++) {
            int idx = tid + l * 256;
            int r = idx >> 3, c = idx & 7;
            int gr = row0 + r;
            float4 a = make_float4(0.f, 0.f, 0.f, 0.f);
            if (gr < n) a = *(const float4*)(A + (size_t)gr * 128 + k0 + c * 4);
            if (RELU) {
                a.x = fmaxf(a.x, 0.f); a.y = fmaxf(a.y, 0.f);
                a.z = fmaxf(a.z, 0.f); a.w = fmaxf(a.w, 0.f);
            }
            As[r][c * 4 + 0] = a.x; As[r][c * 4 + 1] = a.y;
            As[r][c * 4 + 2] = a.z; As[r][c * 4 + 3] = a.w;
        }
        __syncthreads();
#pragma unroll
        for (int k = 0; k < 32; k++) {
            float a0 = As[ty * 2 + 0][k];
            float a1 = As[ty * 2 + 1][k];
            float wv[5];
#pragma unroll
            for (int j = 0; j < 5; j++) wv[j] = Ws[k0 + k][tx * 5 + j];
#pragma unroll
            for (int j = 0; j < 5; j++) {
                acc[0][j] += a0 * wv[j];
                acc[1][j] += a1 * wv[j];
            }
        }
        __syncthreads();
    }

#pragma unroll
    for (int i = 0; i < 2; i++) {
        int gr = row0 + ty * 2 + i;
        if (gr >= n) continue;
        float di = g_dinv[gr];
        float dd = di * di;
#pragma unroll
        for (int j = 0; j < 5; j++) {
            int c = tx * 5 + j;
            float h = acc[i][j];
            H2[(size_t)gr * 40 + c]  = h;
            OUT[(size_t)gr * 40 + c] = h * dd + b[c];
        }
    }
}

// ------------------------------------------------------------------
// SpMM aggregation: AGG[d] += sum_{s in csr row d} dinv[s]*dinv[d]*H[s]
// one warp per dst node, no atomics, in-place over AGG
// ------------------------------------------------------------------
__global__ __launch_bounds__(256)
void k_spmm128(const float* __restrict__ h, float* __restrict__ agg, int n) {
    int w = (blockIdx.x * blockDim.x + threadIdx.x) >> 5;
    if (w >= n) return;
    int lane = threadIdx.x & 31;
    int beg = g_rowptr[w];
    int end = g_rowptr[w + 1];
    float dd = g_dinv[w];
    float4 acc = *(const float4*)(agg + (size_t)w * 128 + lane * 4);

    int idx = beg;
    for (; idx + 4 <= end; idx += 4) {
        int s0 = g_csr[idx + 0], s1 = g_csr[idx + 1];
        int s2 = g_csr[idx + 2], s3 = g_csr[idx + 3];
        float n0 = g_dinv[s0] * dd, n1 = g_dinv[s1] * dd;
        float n2 = g_dinv[s2] * dd, n3 = g_dinv[s3] * dd;
        float4 v0 = *(const float4*)(h + (size_t)s0 * 128 + lane * 4);
        float4 v1 = *(const float4*)(h + (size_t)s1 * 128 + lane * 4);
        float4 v2 = *(const float4*)(h + (size_t)s2 * 128 + lane * 4);
        float4 v3 = *(const float4*)(h + (size_t)s3 * 128 + lane * 4);
        acc.x += n0 * v0.x; acc.y += n0 * v0.y; acc.z += n0 * v0.z; acc.w += n0 * v0.w;
        acc.x += n1 * v1.x; acc.y += n1 * v1.y; acc.z += n1 * v1.z; acc.w += n1 * v1.w;
        acc.x += n2 * v2.x; acc.y += n2 * v2.y; acc.z += n2 * v2.z; acc.w += n2 * v2.w;
        acc.x += n3 * v3.x; acc.y += n3 * v3.y; acc.z += n3 * v3.z; acc.w += n3 * v3.w;
    }
    for (; idx < end; ++idx) {
        int s = g_csr[idx];
        float nr = g_dinv[s] * dd;
        float4 v = *(const float4*)(h + (size_t)s * 128 + lane * 4);
        acc.x += nr * v.x; acc.y += nr * v.y; acc.z += nr * v.z; acc.w += nr * v.w;
    }
    *(float4*)(agg + (size_t)w * 128 + lane * 4) = acc;
}

__global__ __launch_bounds__(256)
void k_spmm40(const float* __restrict__ h, float* __restrict__ out, int n) {
    int w = (blockIdx.x * blockDim.x + threadIdx.x) >> 5;
    if (w >= n) return;
    int lane = threadIdx.x & 31;
    if (lane >= 20) return;
    int beg = g_rowptr[w];
    int end = g_rowptr[w + 1];
    float dd = g_dinv[w];
    float2 acc = *(const float2*)(out + (size_t)w * 40 + lane * 2);

    int idx = beg;
    for (; idx + 4 <= end; idx += 4) {
        int s0 = g_csr[idx + 0], s1 = g_csr[idx + 1];
        int s2 = g_csr[idx + 2], s3 = g_csr[idx + 3];
        float n0 = g_dinv[s0] * dd, n1 = g_dinv[s1] * dd;
        float n2 = g_dinv[s2] * dd, n3 = g_dinv[s3] * dd;
        float2 v0 = *(const float2*)(h + (size_t)s0 * 40 + lane * 2);
        float2 v1 = *(const float2*)(h + (size_t)s1 * 40 + lane * 2);
        float2 v2 = *(const float2*)(h + (size_t)s2 * 40 + lane * 2);
        float2 v3 = *(const float2*)(h + (size_t)s3 * 40 + lane * 2);
        acc.x += n0 * v0.x; acc.y += n0 * v0.y;
        acc.x += n1 * v1.x; acc.y += n1 * v1.y;
        acc.x += n2 * v2.x; acc.y += n2 * v2.y;
        acc.x += n3 * v3.x; acc.y += n3 * v3.y;
    }
    for (; idx < end; ++idx) {
        int s = g_csr[idx];
        float nr = g_dinv[s] * dd;
        float2 v = *(const float2*)(h + (size_t)s * 40 + lane * 2);
        acc.x += nr * v.x; acc.y += nr * v.y;
    }
    *(float2*)(out + (size_t)w * 40 + lane * 2) = acc;
}

// ------------------------------------------------------------------
extern "C" void kernel_launch(void* const* d_in, const int* in_sizes, int n_in,
                              void* d_out, int out_size) {
    const float* x  = (const float*)d_in[0];
    const float* W0 = (const float*)d_in[1];
    const float* b0 = (const float*)d_in[2];
    const float* W1 = (const float*)d_in[3];
    const float* b1 = (const float*)d_in[4];
    const float* W2 = (const float*)d_in[5];
    const float* b2 = (const float*)d_in[6];
    const void*  ei = d_in[7];
    int n = in_sizes[0] / FEAT;
    int E = in_sizes[7] / 2;
    if (E > EMAX) E = EMAX;
    float* out = (float*)d_out;

    float *pH, *pAGG, *pH2;
    cudaGetSymbolAddress((void**)&pH,   g_H);
    cudaGetSymbolAddress((void**)&pAGG, g_AGG);
    cudaGetSymbolAddress((void**)&pH2,  g_H2);

    const int tb = 256;
    int nblk  = (n + tb - 1) / tb;
    int eblk  = (E + tb - 1) / tb;
    int gblk  = (n + 63) / 64;
    int scblk = (n + 1023) / 1024;
    int wblk  = (int)(((long long)n * 32 + tb - 1) / tb);

    // degree + CSR build
    k_zero_deg<<<nblk, tb>>>(ei, n);
    k_count<<<eblk, tb>>>(ei, E);
    k_dinv<<<nblk, tb>>>(n);
    k_scanA<<<scblk, 1024>>>(n);
    k_scanB<<<1, 32>>>(scblk);
    k_scanC<<<scblk, 1024>>>(n, E);
    k_fill<<<eblk, tb>>>(ei, E);

    // layer 0
    k_gemm128<false><<<gblk, 256>>>(x, W0, b0, pH, pAGG, n);
    k_spmm128<<<wblk, tb>>>(pH, pAGG, n);
    // layer 1 (ReLU fused into next GEMM's A-load)
    k_gemm128<true><<<gblk, 256>>>(pAGG, W1, b1, pH, pAGG, n);
    k_spmm128<<<wblk, tb>>>(pH, pAGG, n);
    // layer 2
    k_gemm40<true><<<gblk, 256>>>(pAGG, W2, b2, pH2, out, n);
    k_spmm40<<<wblk, tb>>>(pH2, out, n);
}

// round 3
// speedup vs baseline: 3.0203x; 1.1500x over previous
#include <cuda_runtime.h>

#define NN    100000
#define FEAT  128
#define CLS   40
#define EMAX  1600000

// ---- scratch (static device globals; no allocation allowed) ----
__device__ int   g_degi[NN];
__device__ float g_dinv[NN];
__device__ float g_H[(size_t)NN * FEAT];    // GEMM output (messages source)
__device__ float g_AGG[(size_t)NN * FEAT];  // aggregation buffer
__device__ float g_H2[(size_t)NN * CLS];    // last-layer GEMM output
__device__ int   g_is64;                    // edge_index dtype flag
__device__ int   g_rowptr[NN + 1];
__device__ int   g_cursor[NN];
__device__ int   g_csr[EMAX];               // src ids grouped by dst
__device__ int   g_bsum[128];
__device__ int   g_boff[128];

// ------------------------------------------------------------------
// degree / dinv / CSR build
// ------------------------------------------------------------------
__global__ void k_zero_deg(const void* ei, int n) {
    int i = blockIdx.x * blockDim.x + threadIdx.x;
    if (i < n) g_degi[i] = 0;
    if (i == 0) {
        // int64 vs int32 detection: int32 data viewed as u64 words holds two
        // random values in [0,N) -> word >= 2^32 almost surely. Check 2 words.
        const unsigned long long* p = (const unsigned long long*)ei;
        g_is64 = (p[0] < (unsigned long long)n && p[1] < (unsigned long long)n) ? 1 : 0;
    }
}

__global__ void k_count(const void* ei, int E) {
    int e = blockIdx.x * blockDim.x + threadIdx.x;
    if (e >= E) return;
    int dst;
    if (g_is64) dst = (int)((const long long*)ei)[E + e];
    else        dst = ((const int*)ei)[E + e];
    atomicAdd(&g_degi[dst], 1);
}

__global__ void k_dinv(int n) {
    int i = blockIdx.x * blockDim.x + threadIdx.x;
    if (i < n) g_dinv[i] = rsqrtf((float)g_degi[i] + 1.f);
}

// exclusive scan of g_degi -> g_rowptr, 3 phases
__global__ void k_scanA(int n) {
    __shared__ int s[1024];
    int i = blockIdx.x * 1024 + threadIdx.x;
    int v = (i < n) ? g_degi[i] : 0;
    s[threadIdx.x] = v;
    __syncthreads();
#pragma unroll
    for (int off = 1; off < 1024; off <<= 1) {
        int x = (threadIdx.x >= off) ? s[threadIdx.x - off] : 0;
        __syncthreads();
        s[threadIdx.x] += x;
        __syncthreads();
    }
    if (i < n) g_rowptr[i] = s[threadIdx.x] - v;      // exclusive within block
    if (threadIdx.x == 1023) g_bsum[blockIdx.x] = s[1023];
}

__global__ void k_scanB(int nb) {
    if (threadIdx.x == 0) {
        int acc = 0;
        for (int b = 0; b < nb; b++) { int t = g_bsum[b]; g_boff[b] = acc; acc += t; }
    }
}

__global__ void k_scanC(int n, int E) {
    int i = blockIdx.x * 1024 + threadIdx.x;
    if (i < n) {
        int r = g_rowptr[i] + g_boff[blockIdx.x];
        g_rowptr[i] = r;
        g_cursor[i] = r;
    }
    if (i == 0) g_rowptr[n] = E;
}

__global__ void k_fill(const void* ei, int E) {
    int e = blockIdx.x * blockDim.x + threadIdx.x;
    if (e >= E) return;
    int s, d;
    if (g_is64) {
        const long long* p = (const long long*)ei;
        s = (int)p[e]; d = (int)p[E + e];
    } else {
        const int* p = (const int*)ei;
        s = p[e]; d = p[E + e];
    }
    int pos = atomicAdd(&g_cursor[d], 1);
    g_csr[pos] = s;
}

// ------------------------------------------------------------------
// GEMM (K=128, Nout=128): H = act(A) @ W ; AGG = H * dinv^2 + b
// BM=128, BN=128, BK=16, thread tile 8x8, 256 threads, 2 CTAs/SM
// ------------------------------------------------------------------
template <bool RELU>
__global__ __launch_bounds__(256, 2)
void k_gemm128(const float* __restrict__ A, const float* __restrict__ W,
               const float* __restrict__ b, float* __restrict__ H,
               float* __restrict__ AGG, int n) {
    __shared__ float As[16][128];   // transposed: As[k][m]
    __shared__ float Ws[16][128];   // Ws[k][nc]
    const int tid = threadIdx.x;
    const int tx = tid & 15;        // col group: cols tx*8 .. +7
    const int ty = tid >> 4;        // row group: rows ty*8 .. +7
    const int row0 = blockIdx.x * 128;
    const int ar = tid >> 2;        // 0..63 : A row within half-tile
    const int ac = tid & 3;         // 0..3  : float4 index within 16 k
    const int wr = tid >> 5;        // 0..7  : W k-row within half-chunk
    const int wc = tid & 31;        // 0..31 : float4 col

    float acc[8][8];
#pragma unroll
    for (int i = 0; i < 8; i++)
#pragma unroll
        for (int j = 0; j < 8; j++) acc[i][j] = 0.f;

    for (int k0 = 0; k0 < 128; k0 += 16) {
        float4 av4[2], wv4[2];
#pragma unroll
        for (int l = 0; l < 2; l++) {
            int gr = row0 + ar + l * 64;
            float4 a = make_float4(0.f, 0.f, 0.f, 0.f);
            if (gr < n) a = *(const float4*)(A + (size_t)gr * 128 + k0 + ac * 4);
            if (RELU) {
                a.x = fmaxf(a.x, 0.f); a.y = fmaxf(a.y, 0.f);
                a.z = fmaxf(a.z, 0.f); a.w = fmaxf(a.w, 0.f);
            }
            av4[l] = a;
        }
#pragma unroll
        for (int l = 0; l < 2; l++)
            wv4[l] = *(const float4*)(W + (size_t)(k0 + wr + l * 8) * 128 + wc * 4);

        __syncthreads();   // previous compute done reading smem
#pragma unroll
        for (int l = 0; l < 2; l++) {
            int r = ar + l * 64;
            As[ac * 4 + 0][r] = av4[l].x;
            As[ac * 4 + 1][r] = av4[l].y;
            As[ac * 4 + 2][r] = av4[l].z;
            As[ac * 4 + 3][r] = av4[l].w;
            *(float4*)&Ws[wr + l * 8][wc * 4] = wv4[l];
        }
        __syncthreads();

#pragma unroll
        for (int k = 0; k < 16; k++) {
            float4 a0 = *(const float4*)&As[k][ty * 8];
            float4 a1 = *(const float4*)&As[k][ty * 8 + 4];
            float4 w0 = *(const float4*)&Ws[k][tx * 8];
            float4 w1 = *(const float4*)&Ws[k][tx * 8 + 4];
            float av[8] = {a0.x, a0.y, a0.z, a0.w, a1.x, a1.y, a1.z, a1.w};
            float wv[8] = {w0.x, w0.y, w0.z, w0.w, w1.x, w1.y, w1.z, w1.w};
#pragma unroll
            for (int i = 0; i < 8; i++)
#pragma unroll
                for (int j = 0; j < 8; j++) acc[i][j] += av[i] * wv[j];
        }
    }

    float4 bv0 = *(const float4*)(b + tx * 8);
    float4 bv1 = *(const float4*)(b + tx * 8 + 4);
#pragma unroll
    for (int i = 0; i < 8; i++) {
        int gr = row0 + ty * 8 + i;
        if (gr >= n) continue;
        float di = g_dinv[gr];
        float dd = di * di;
        float4 h0 = make_float4(acc[i][0], acc[i][1], acc[i][2], acc[i][3]);
        float4 h1 = make_float4(acc[i][4], acc[i][5], acc[i][6], acc[i][7]);
        *(float4*)(H + (size_t)gr * 128 + tx * 8)     = h0;
        *(float4*)(H + (size_t)gr * 128 + tx * 8 + 4) = h1;
        float4 g0 = make_float4(h0.x * dd + bv0.x, h0.y * dd + bv0.y,
                                h0.z * dd + bv0.z, h0.w * dd + bv0.w);
        float4 g1 = make_float4(h1.x * dd + bv1.x, h1.y * dd + bv1.y,
                                h1.z * dd + bv1.z, h1.w * dd + bv1.w);
        *(float4*)(AGG + (size_t)gr * 128 + tx * 8)     = g0;
        *(float4*)(AGG + (size_t)gr * 128 + tx * 8 + 4) = g1;
    }
}

// ------------------------------------------------------------------
// GEMM (K=128, Nout=40): H2 = relu(A) @ W2 ; OUT = H2 * dinv^2 + b2
// BM=128, BK=16, thread tile 4x5, W fully resident in smem
// ------------------------------------------------------------------
template <bool RELU>
__global__ __launch_bounds__(256)
void k_gemm40(const float* __restrict__ A, const float* __restrict__ W,
              const float* __restrict__ b, float* __restrict__ H2,
              float* __restrict__ OUT, int n) {
    __shared__ float As[16][128];   // transposed: As[k][m]
    __shared__ float Ws[128][40];
    const int tid = threadIdx.x;
    const int tx = tid & 7;         // col group: cols tx*5 .. +4
    const int ty = tid >> 3;        // row group (0..31): rows ty*4 .. +3
    const int row0 = blockIdx.x * 128;
    const int ar = tid >> 2;
    const int ac = tid & 3;

    for (int idx = tid; idx < 128 * 40; idx += 256)
        Ws[idx / 40][idx % 40] = W[idx];

    float acc[4][5];
#pragma unroll
    for (int i = 0; i < 4; i++)
#pragma unroll
        for (int j = 0; j < 5; j++) acc[i][j] = 0.f;

    for (int k0 = 0; k0 < 128; k0 += 16) {
        float4 av4[2];
#pragma unroll
        for (int l = 0; l < 2; l++) {
            int gr = row0 + ar + l * 64;
            float4 a = make_float4(0.f, 0.f, 0.f, 0.f);
            if (gr < n) a = *(const float4*)(A + (size_t)gr * 128 + k0 + ac * 4);
            if (RELU) {
                a.x = fmaxf(a.x, 0.f); a.y = fmaxf(a.y, 0.f);
                a.z = fmaxf(a.z, 0.f); a.w = fmaxf(a.w, 0.f);
            }
            av4[l] = a;
        }
        __syncthreads();
#pragma unroll
        for (int l = 0; l < 2; l++) {
            int r = ar + l * 64;
            As[ac * 4 + 0][r] = av4[l].x;
            As[ac * 4 + 1][r] = av4[l].y;
            As[ac * 4 + 2][r] = av4[l].z;
            As[ac * 4 + 3][r] = av4[l].w;
        }
        __syncthreads();
#pragma unroll
        for (int k = 0; k < 16; k++) {
            float4 a0 = *(const float4*)&As[k][ty * 4];
            float av[4] = {a0.x, a0.y, a0.z, a0.w};
            float wv[5];
#pragma unroll
            for (int j = 0; j < 5; j++) wv[j] = Ws[k0 + k][tx * 5 + j];
#pragma unroll
            for (int i = 0; i < 4; i++)
#pragma unroll
                for (int j = 0; j < 5; j++) acc[i][j] += av[i] * wv[j];
        }
        __syncthreads();
    }

#pragma unroll
    for (int i = 0; i < 4; i++) {
        int gr = row0 + ty * 4 + i;
        if (gr >= n) continue;
        float di = g_dinv[gr];
        float dd = di * di;
#pragma unroll
        for (int j = 0; j < 5; j++) {
            int c = tx * 5 + j;
            float h = acc[i][j];
            H2[(size_t)gr * 40 + c]  = h;
            OUT[(size_t)gr * 40 + c] = h * dd + b[c];
        }
    }
}

// ------------------------------------------------------------------
// SpMM aggregation: AGG[d] += sum_{s in csr row d} dinv[s]*dinv[d]*H[s]
// one warp per dst node, no atomics, in-place over AGG
// ------------------------------------------------------------------
__global__ __launch_bounds__(256)
void k_spmm128(const float* __restrict__ h, float* __restrict__ agg, int n) {
    int w = (blockIdx.x * blockDim.x + threadIdx.x) >> 5;
    if (w >= n) return;
    int lane = threadIdx.x & 31;
    int beg = g_rowptr[w];
    int end = g_rowptr[w + 1];
    float dd = g_dinv[w];
    float4 acc = *(const float4*)(agg + (size_t)w * 128 + lane * 4);

    int idx = beg;
    for (; idx + 4 <= end; idx += 4) {
        int s0 = g_csr[idx + 0], s1 = g_csr[idx + 1];
        int s2 = g_csr[idx + 2], s3 = g_csr[idx + 3];
        float n0 = g_dinv[s0] * dd, n1 = g_dinv[s1] * dd;
        float n2 = g_dinv[s2] * dd, n3 = g_dinv[s3] * dd;
        float4 v0 = *(const float4*)(h + (size_t)s0 * 128 + lane * 4);
        float4 v1 = *(const float4*)(h + (size_t)s1 * 128 + lane * 4);
        float4 v2 = *(const float4*)(h + (size_t)s2 * 128 + lane * 4);
        float4 v3 = *(const float4*)(h + (size_t)s3 * 128 + lane * 4);
        acc.x += n0 * v0.x; acc.y += n0 * v0.y; acc.z += n0 * v0.z; acc.w += n0 * v0.w;
        acc.x += n1 * v1.x; acc.y += n1 * v1.y; acc.z += n1 * v1.z; acc.w += n1 * v1.w;
        acc.x += n2 * v2.x; acc.y += n2 * v2.y; acc.z += n2 * v2.z; acc.w += n2 * v2.w;
        acc.x += n3 * v3.x; acc.y += n3 * v3.y; acc.z += n3 * v3.z; acc.w += n3 * v3.w;
    }
    for (; idx < end; ++idx) {
        int s = g_csr[idx];
        float nr = g_dinv[s] * dd;
        float4 v = *(const float4*)(h + (size_t)s * 128 + lane * 4);
        acc.x += nr * v.x; acc.y += nr * v.y; acc.z += nr * v.z; acc.w += nr * v.w;
    }
    *(float4*)(agg + (size_t)w * 128 + lane * 4) = acc;
}

__global__ __launch_bounds__(256)
void k_spmm40(const float* __restrict__ h, float* __restrict__ out, int n) {
    int w = (blockIdx.x * blockDim.x + threadIdx.x) >> 5;
    if (w >= n) return;
    int lane = threadIdx.x & 31;
    if (lane >= 20) return;
    int beg = g_rowptr[w];
    int end = g_rowptr[w + 1];
    float dd = g_dinv[w];
    float2 acc = *(const float2*)(out + (size_t)w * 40 + lane * 2);

    int idx = beg;
    for (; idx + 4 <= end; idx += 4) {
        int s0 = g_csr[idx + 0], s1 = g_csr[idx + 1];
        int s2 = g_csr[idx + 2], s3 = g_csr[idx + 3];
        float n0 = g_dinv[s0] * dd, n1 = g_dinv[s1] * dd;
        float n2 = g_dinv[s2] * dd, n3 = g_dinv[s3] * dd;
        float2 v0 = *(const float2*)(h + (size_t)s0 * 40 + lane * 2);
        float2 v1 = *(const float2*)(h + (size_t)s1 * 40 + lane * 2);
        float2 v2 = *(const float2*)(h + (size_t)s2 * 40 + lane * 2);
        float2 v3 = *(const float2*)(h + (size_t)s3 * 40 + lane * 2);
        acc.x += n0 * v0.x; acc.y += n0 * v0.y;
        acc.x += n1 * v1.x; acc.y += n1 * v1.y;
        acc.x += n2 * v2.x; acc.y += n2 * v2.y;
        acc.x += n3 * v3.x; acc.y += n3 * v3.y;
    }
    for (; idx < end; ++idx) {
        int s = g_csr[idx];
        float nr = g_dinv[s] * dd;
        float2 v = *(const float2*)(h + (size_t)s * 40 + lane * 2);
        acc.x += nr * v.x; acc.y += nr * v.y;
    }
    *(float2*)(out + (size_t)w * 40 + lane * 2) = acc;
}

// ------------------------------------------------------------------
extern "C" void kernel_launch(void* const* d_in, const int* in_sizes, int n_in,
                              void* d_out, int out_size) {
    const float* x  = (const float*)d_in[0];
    const float* W0 = (const float*)d_in[1];
    const float* b0 = (const float*)d_in[2];
    const float* W1 = (const float*)d_in[3];
    const float* b1 = (const float*)d_in[4];
    const float* W2 = (const float*)d_in[5];
    const float* b2 = (const float*)d_in[6];
    const void*  ei = d_in[7];
    int n = in_sizes[0] / FEAT;
    int E = in_sizes[7] / 2;
    if (E > EMAX) E = EMAX;
    float* out = (float*)d_out;

    float *pH, *pAGG, *pH2;
    cudaGetSymbolAddress((void**)&pH,   g_H);
    cudaGetSymbolAddress((void**)&pAGG, g_AGG);
    cudaGetSymbolAddress((void**)&pH2,  g_H2);

    const int tb = 256;
    int nblk  = (n + tb - 1) / tb;
    int eblk  = (E + tb - 1) / tb;
    int gblk  = (n + 127) / 128;
    int scblk = (n + 1023) / 1024;
    int wblk  = (int)(((long long)n * 32 + tb - 1) / tb);

    // degree + CSR build
    k_zero_deg<<<nblk, tb>>>(ei, n);
    k_count<<<eblk, tb>>>(ei, E);
    k_dinv<<<nblk, tb>>>(n);
    k_scanA<<<scblk, 1024>>>(n);
    k_scanB<<<1, 32>>>(scblk);
    k_scanC<<<scblk, 1024>>>(n, E);
    k_fill<<<eblk, tb>>>(ei, E);

    // layer 0
    k_gemm128<false><<<gblk, 256>>>(x, W0, b0, pH, pAGG, n);
    k_spmm128<<<wblk, tb>>>(pH, pAGG, n);
    // layer 1 (ReLU fused into next GEMM's A-load; in-place over AGG is safe:
    // each block reads only the rows it later writes)
    k_gemm128<true><<<gblk, 256>>>(pAGG, W1, b1, pH, pAGG, n);
    k_spmm128<<<wblk, tb>>>(pH, pAGG, n);
    // layer 2
    k_gemm40<true><<<gblk, 256>>>(pAGG, W2, b2, pH2, out, n);
    k_spmm40<<<wblk, tb>>>(pH2, out, n);
}

// round 4
// speedup vs baseline: 3.4567x; 1.1445x over previous
#include <cuda_runtime.h>
#include <cuda_fp16.h>

#define NN    100000
#define FEAT  128
#define CLS   40
#define EMAX  1600000

// ---- scratch (static device globals; no allocation allowed) ----
__device__ int    g_degi[NN];
__device__ float  g_dinv[NN];
__device__ __half g_Hh[(size_t)NN * FEAT];   // pre-scaled fp16 messages h*dinv
__device__ float  g_AGG[(size_t)NN * FEAT];  // aggregation buffer
__device__ float  g_H2[(size_t)NN * CLS];    // last-layer GEMM output (fp32)
__device__ int    g_is64;                    // edge_index dtype flag
__device__ int    g_rowptr[NN + 1];
__device__ int    g_cursor[NN];
__device__ int    g_csr[EMAX];               // src ids grouped by dst
__device__ int    g_bsum[128];
__device__ int    g_boff[128];

// ---- packed f32x2 helpers (Blackwell FFMA2 path) ----
__device__ __forceinline__ unsigned long long pk_dup(float v) {
    unsigned long long r;
    asm("mov.b64 %0, {%1, %1};" : "=l"(r) : "f"(v));
    return r;
}
__device__ __forceinline__ void fma2(unsigned long long& d,
                                     unsigned long long a,
                                     unsigned long long b) {
    asm("fma.rn.f32x2 %0, %1, %2, %0;" : "+l"(d) : "l"(a), "l"(b));
}
__device__ __forceinline__ void unpk(float& lo, float& hi, unsigned long long p) {
    asm("mov.b64 {%0, %1}, %2;" : "=f"(lo), "=f"(hi) : "l"(p));
}

// ------------------------------------------------------------------
// degree / dinv / CSR build
// ------------------------------------------------------------------
__global__ void k_zero_deg(const void* ei, int n) {
    int i = blockIdx.x * blockDim.x + threadIdx.x;
    if (i < n) g_degi[i] = 0;
    if (i == 0) {
        const unsigned long long* p = (const unsigned long long*)ei;
        g_is64 = (p[0] < (unsigned long long)n && p[1] < (unsigned long long)n) ? 1 : 0;
    }
}

__global__ void k_count(const void* ei, int E) {
    int e = blockIdx.x * blockDim.x + threadIdx.x;
    if (e >= E) return;
    int dst;
    if (g_is64) dst = (int)((const long long*)ei)[E + e];
    else        dst = ((const int*)ei)[E + e];
    atomicAdd(&g_degi[dst], 1);
}

__global__ void k_dinv(int n) {
    int i = blockIdx.x * blockDim.x + threadIdx.x;
    if (i < n) g_dinv[i] = rsqrtf((float)g_degi[i] + 1.f);
}

__global__ void k_scanA(int n) {
    __shared__ int s[1024];
    int i = blockIdx.x * 1024 + threadIdx.x;
    int v = (i < n) ? g_degi[i] : 0;
    s[threadIdx.x] = v;
    __syncthreads();
#pragma unroll
    for (int off = 1; off < 1024; off <<= 1) {
        int x = (threadIdx.x >= off) ? s[threadIdx.x - off] : 0;
        __syncthreads();
        s[threadIdx.x] += x;
        __syncthreads();
    }
    if (i < n) g_rowptr[i] = s[threadIdx.x] - v;
    if (threadIdx.x == 1023) g_bsum[blockIdx.x] = s[1023];
}

__global__ void k_scanB(int nb) {
    if (threadIdx.x == 0) {
        int acc = 0;
        for (int b = 0; b < nb; b++) { int t = g_bsum[b]; g_boff[b] = acc; acc += t; }
    }
}

__global__ void k_scanC(int n, int E) {
    int i = blockIdx.x * 1024 + threadIdx.x;
    if (i < n) {
        int r = g_rowptr[i] + g_boff[blockIdx.x];
        g_rowptr[i] = r;
        g_cursor[i] = r;
    }
    if (i == 0) g_rowptr[n] = E;
}

__global__ void k_fill(const void* ei, int E) {
    int e = blockIdx.x * blockDim.x + threadIdx.x;
    if (e >= E) return;
    int s, d;
    if (g_is64) {
        const long long* p = (const long long*)ei;
        s = (int)p[e]; d = (int)p[E + e];
    } else {
        const int* p = (const int*)ei;
        s = p[e]; d = p[E + e];
    }
    int pos = atomicAdd(&g_cursor[d], 1);
    g_csr[pos] = s;
}

// ------------------------------------------------------------------
// GEMM (K=128, Nout=128): h = act(A) @ W
//   Hh  = half(h * dinv)          (pre-scaled message)
//   AGG = h * dinv^2 + b          (self-loop + bias, fp32)
// BM=128, BN=128, BK=16, thread tile 8x8 via packed f32x2, 256 thr
// ------------------------------------------------------------------
template <bool RELU>
__global__ __launch_bounds__(256, 2)
void k_gemm128(const float* __restrict__ A, const float* __restrict__ W,
               const float* __restrict__ b, __half* __restrict__ Hh,
               float* __restrict__ AGG, int n) {
    __shared__ float As[16][128];   // transposed: As[k][m]
    __shared__ float Ws[16][128];   // Ws[k][nc]
    const int tid = threadIdx.x;
    const int tx = tid & 15;        // col group: cols tx*8 .. +7
    const int ty = tid >> 4;        // row group: rows ty*8 .. +7
    const int row0 = blockIdx.x * 128;
    const int ar = tid >> 2;        // 0..63
    const int ac = tid & 3;         // 0..3
    const int wr = tid >> 5;        // 0..7
    const int wc = tid & 31;        // 0..31

    // acc[p][j]: row-pair p (rows ty*8+2p, +2p+1), col tx*8+j
    unsigned long long acc[4][8];
#pragma unroll
    for (int p = 0; p < 4; p++)
#pragma unroll
        for (int j = 0; j < 8; j++) acc[p][j] = 0ull;

    for (int k0 = 0; k0 < 128; k0 += 16) {
        float4 av4[2], wv4[2];
#pragma unroll
        for (int l = 0; l < 2; l++) {
            int gr = row0 + ar + l * 64;
            float4 a = make_float4(0.f, 0.f, 0.f, 0.f);
            if (gr < n) a = *(const float4*)(A + (size_t)gr * 128 + k0 + ac * 4);
            if (RELU) {
                a.x = fmaxf(a.x, 0.f); a.y = fmaxf(a.y, 0.f);
                a.z = fmaxf(a.z, 0.f); a.w = fmaxf(a.w, 0.f);
            }
            av4[l] = a;
        }
#pragma unroll
        for (int l = 0; l < 2; l++)
            wv4[l] = *(const float4*)(W + (size_t)(k0 + wr + l * 8) * 128 + wc * 4);

        __syncthreads();
#pragma unroll
        for (int l = 0; l < 2; l++) {
            int r = ar + l * 64;
            As[ac * 4 + 0][r] = av4[l].x;
            As[ac * 4 + 1][r] = av4[l].y;
            As[ac * 4 + 2][r] = av4[l].z;
            As[ac * 4 + 3][r] = av4[l].w;
            *(float4*)&Ws[wr + l * 8][wc * 4] = wv4[l];
        }
        __syncthreads();

#pragma unroll
        for (int k = 0; k < 16; k++) {
            // A row pairs straight from smem (rows adjacent in As[k][*])
            ulonglong2 a01 = *(const ulonglong2*)&As[k][ty * 8];
            ulonglong2 a23 = *(const ulonglong2*)&As[k][ty * 8 + 4];
            unsigned long long ap[4] = {a01.x, a01.y, a23.x, a23.y};
            float4 w0 = *(const float4*)&Ws[k][tx * 8];
            float4 w1 = *(const float4*)&Ws[k][tx * 8 + 4];
            unsigned long long wp[8];
            wp[0] = pk_dup(w0.x); wp[1] = pk_dup(w0.y);
            wp[2] = pk_dup(w0.z); wp[3] = pk_dup(w0.w);
            wp[4] = pk_dup(w1.x); wp[5] = pk_dup(w1.y);
            wp[6] = pk_dup(w1.z); wp[7] = pk_dup(w1.w);
#pragma unroll
            for (int p = 0; p < 4; p++)
#pragma unroll
                for (int j = 0; j < 8; j++) fma2(acc[p][j], ap[p], wp[j]);
        }
    }

    float4 bv0 = *(const float4*)(b + tx * 8);
    float4 bv1 = *(const float4*)(b + tx * 8 + 4);
    float bb[8] = {bv0.x, bv0.y, bv0.z, bv0.w, bv1.x, bv1.y, bv1.z, bv1.w};

#pragma unroll
    for (int p = 0; p < 4; p++) {
        float lo[8], hi[8];
#pragma unroll
        for (int j = 0; j < 8; j++) unpk(lo[j], hi[j], acc[p][j]);
#pragma unroll
        for (int half_sel = 0; half_sel < 2; half_sel++) {
            int gr = row0 + ty * 8 + 2 * p + half_sel;
            if (gr >= n) continue;
            const float* hv = half_sel ? hi : lo;
            float di = g_dinv[gr];
            float dd = di * di;
            // pre-scaled fp16 message row
            __half2 hh[4];
#pragma unroll
            for (int c = 0; c < 4; c++)
                hh[c] = __floats2half2_rn(hv[2 * c] * di, hv[2 * c + 1] * di);
            *(uint4*)(Hh + (size_t)gr * 128 + tx * 8) = *(uint4*)hh;
            // fp32 self-loop + bias
            float4 g0 = make_float4(hv[0] * dd + bb[0], hv[1] * dd + bb[1],
                                    hv[2] * dd + bb[2], hv[3] * dd + bb[3]);
            float4 g1 = make_float4(hv[4] * dd + bb[4], hv[5] * dd + bb[5],
                                    hv[6] * dd + bb[6], hv[7] * dd + bb[7]);
            *(float4*)(AGG + (size_t)gr * 128 + tx * 8)     = g0;
            *(float4*)(AGG + (size_t)gr * 128 + tx * 8 + 4) = g1;
        }
    }
}

// ------------------------------------------------------------------
// GEMM (K=128, Nout=40): H2 = relu(A) @ W2 ; OUT = H2 * dinv^2 + b2
// ------------------------------------------------------------------
template <bool RELU>
__global__ __launch_bounds__(256)
void k_gemm40(const float* __restrict__ A, const float* __restrict__ W,
              const float* __restrict__ b, float* __restrict__ H2,
              float* __restrict__ OUT, int n) {
    __shared__ float As[16][128];
    __shared__ float Ws[128][40];
    const int tid = threadIdx.x;
    const int tx = tid & 7;
    const int ty = tid >> 3;
    const int row0 = blockIdx.x * 128;
    const int ar = tid >> 2;
    const int ac = tid & 3;

    for (int idx = tid; idx < 128 * 40; idx += 256)
        Ws[idx / 40][idx % 40] = W[idx];

    float acc[4][5];
#pragma unroll
    for (int i = 0; i < 4; i++)
#pragma unroll
        for (int j = 0; j < 5; j++) acc[i][j] = 0.f;

    for (int k0 = 0; k0 < 128; k0 += 16) {
        float4 av4[2];
#pragma unroll
        for (int l = 0; l < 2; l++) {
            int gr = row0 + ar + l * 64;
            float4 a = make_float4(0.f, 0.f, 0.f, 0.f);
            if (gr < n) a = *(const float4*)(A + (size_t)gr * 128 + k0 + ac * 4);
            if (RELU) {
                a.x = fmaxf(a.x, 0.f); a.y = fmaxf(a.y, 0.f);
                a.z = fmaxf(a.z, 0.f); a.w = fmaxf(a.w, 0.f);
            }
            av4[l] = a;
        }
        __syncthreads();
#pragma unroll
        for (int l = 0; l < 2; l++) {
            int r = ar + l * 64;
            As[ac * 4 + 0][r] = av4[l].x;
            As[ac * 4 + 1][r] = av4[l].y;
            As[ac * 4 + 2][r] = av4[l].z;
            As[ac * 4 + 3][r] = av4[l].w;
        }
        __syncthreads();
#pragma unroll
        for (int k = 0; k < 16; k++) {
            float4 a0 = *(const float4*)&As[k][ty * 4];
            float av[4] = {a0.x, a0.y, a0.z, a0.w};
            float wv[5];
#pragma unroll
            for (int j = 0; j < 5; j++) wv[j] = Ws[k0 + k][tx * 5 + j];
#pragma unroll
            for (int i = 0; i < 4; i++)
#pragma unroll
                for (int j = 0; j < 5; j++) acc[i][j] += av[i] * wv[j];
        }
        __syncthreads();
    }

#pragma unroll
    for (int i = 0; i < 4; i++) {
        int gr = row0 + ty * 4 + i;
        if (gr >= n) continue;
        float di = g_dinv[gr];
        float dd = di * di;
#pragma unroll
        for (int j = 0; j < 5; j++) {
            int c = tx * 5 + j;
            float h = acc[i][j];
            H2[(size_t)gr * 40 + c]  = h;
            OUT[(size_t)gr * 40 + c] = h * dd + b[c];
        }
    }
}

// ------------------------------------------------------------------
// SpMM aggregation (fp16 pre-scaled messages):
//   AGG[d] += dinv[d] * sum_{s in row d} Hh[s]
// one warp per dst node, lane covers 4 cols (8B), fp32 accumulate
// ------------------------------------------------------------------
__global__ __launch_bounds__(256)
void k_spmm128(const __half* __restrict__ hh, float* __restrict__ agg, int n) {
    int w = (blockIdx.x * blockDim.x + threadIdx.x) >> 5;
    if (w >= n) return;
    int lane = threadIdx.x & 31;
    int beg = g_rowptr[w];
    int end = g_rowptr[w + 1];
    float dd = g_dinv[w];
    float4 acc = make_float4(0.f, 0.f, 0.f, 0.f);

    int idx = beg;
    for (; idx + 4 <= end; idx += 4) {
        int s0 = g_csr[idx + 0], s1 = g_csr[idx + 1];
        int s2 = g_csr[idx + 2], s3 = g_csr[idx + 3];
        uint2 u0 = *(const uint2*)(hh + (size_t)s0 * 128 + lane * 4);
        uint2 u1 = *(const uint2*)(hh + (size_t)s1 * 128 + lane * 4);
        uint2 u2 = *(const uint2*)(hh + (size_t)s2 * 128 + lane * 4);
        uint2 u3 = *(const uint2*)(hh + (size_t)s3 * 128 + lane * 4);
#pragma unroll
        for (int q = 0; q < 4; q++) {
            uint2 u = (q == 0) ? u0 : (q == 1) ? u1 : (q == 2) ? u2 : u3;
            float2 f0 = __half22float2(*(const __half2*)&u.x);
            float2 f1 = __half22float2(*(const __half2*)&u.y);
            acc.x += f0.x; acc.y += f0.y; acc.z += f1.x; acc.w += f1.y;
        }
    }
    for (; idx < end; ++idx) {
        int s = g_csr[idx];
        uint2 u = *(const uint2*)(hh + (size_t)s * 128 + lane * 4);
        float2 f0 = __half22float2(*(const __half2*)&u.x);
        float2 f1 = __half22float2(*(const __half2*)&u.y);
        acc.x += f0.x; acc.y += f0.y; acc.z += f1.x; acc.w += f1.y;
    }
    float* o = agg + (size_t)w * 128 + lane * 4;
    float4 cur = *(const float4*)o;
    cur.x += dd * acc.x; cur.y += dd * acc.y;
    cur.z += dd * acc.z; cur.w += dd * acc.w;
    *(float4*)o = cur;
}

__global__ __launch_bounds__(256)
void k_spmm40(const float* __restrict__ h, float* __restrict__ out, int n) {
    int w = (blockIdx.x * blockDim.x + threadIdx.x) >> 5;
    if (w >= n) return;
    int lane = threadIdx.x & 31;
    if (lane >= 20) return;
    int beg = g_rowptr[w];
    int end = g_rowptr[w + 1];
    float dd = g_dinv[w];
    float2 acc = make_float2(0.f, 0.f);

    int idx = beg;
    for (; idx + 4 <= end; idx += 4) {
        int s0 = g_csr[idx + 0], s1 = g_csr[idx + 1];
        int s2 = g_csr[idx + 2], s3 = g_csr[idx + 3];
        float n0 = g_dinv[s0], n1 = g_dinv[s1];
        float n2 = g_dinv[s2], n3 = g_dinv[s3];
        float2 v0 = *(const float2*)(h + (size_t)s0 * 40 + lane * 2);
        float2 v1 = *(const float2*)(h + (size_t)s1 * 40 + lane * 2);
        float2 v2 = *(const float2*)(h + (size_t)s2 * 40 + lane * 2);
        float2 v3 = *(const float2*)(h + (size_t)s3 * 40 + lane * 2);
        acc.x += n0 * v0.x; acc.y += n0 * v0.y;
        acc.x += n1 * v1.x; acc.y += n1 * v1.y;
        acc.x += n2 * v2.x; acc.y += n2 * v2.y;
        acc.x += n3 * v3.x; acc.y += n3 * v3.y;
    }
    for (; idx < end; ++idx) {
        int s = g_csr[idx];
        float nr = g_dinv[s];
        float2 v = *(const float2*)(h + (size_t)s * 40 + lane * 2);
        acc.x += nr * v.x; acc.y += nr * v.y;
    }
    float* o = out + (size_t)w * 40 + lane * 2;
    float2 cur = *(const float2*)o;
    cur.x += dd * acc.x; cur.y += dd * acc.y;
    *(float2*)o = cur;
}

// ------------------------------------------------------------------
extern "C" void kernel_launch(void* const* d_in, const int* in_sizes, int n_in,
                              void* d_out, int out_size) {
    const float* x  = (const float*)d_in[0];
    const float* W0 = (const float*)d_in[1];
    const float* b0 = (const float*)d_in[2];
    const float* W1 = (const float*)d_in[3];
    const float* b1 = (const float*)d_in[4];
    const float* W2 = (const float*)d_in[5];
    const float* b2 = (const float*)d_in[6];
    const void*  ei = d_in[7];
    int n = in_sizes[0] / FEAT;
    int E = in_sizes[7] / 2;
    if (E > EMAX) E = EMAX;
    float* out = (float*)d_out;

    __half* pHh; float *pAGG, *pH2;
    cudaGetSymbolAddress((void**)&pHh,  g_Hh);
    cudaGetSymbolAddress((void**)&pAGG, g_AGG);
    cudaGetSymbolAddress((void**)&pH2,  g_H2);

    const int tb = 256;
    int nblk  = (n + tb - 1) / tb;
    int eblk  = (E + tb - 1) / tb;
    int gblk  = (n + 127) / 128;
    int scblk = (n + 1023) / 1024;
    int wblk  = (int)(((long long)n * 32 + tb - 1) / tb);

    // degree + CSR build
    k_zero_deg<<<nblk, tb>>>(ei, n);
    k_count<<<eblk, tb>>>(ei, E);
    k_dinv<<<nblk, tb>>>(n);
    k_scanA<<<scblk, 1024>>>(n);
    k_scanB<<<1, 32>>>(scblk);
    k_scanC<<<scblk, 1024>>>(n, E);
    k_fill<<<eblk, tb>>>(ei, E);

    // layer 0
    k_gemm128<false><<<gblk, 256>>>(x, W0, b0, pHh, pAGG, n);
    k_spmm128<<<wblk, tb>>>(pHh, pAGG, n);
    // layer 1 (ReLU fused into next GEMM's A-load)
    k_gemm128<true><<<gblk, 256>>>(pAGG, W1, b1, pHh, pAGG, n);
    k_spmm128<<<wblk, tb>>>(pHh, pAGG, n);
    // layer 2
    k_gemm40<true><<<gblk, 256>>>(pAGG, W2, b2, pH2, out, n);
    k_spmm40<<<wblk, tb>>>(pH2, out, n);
}

// round 5
// speedup vs baseline: 4.2079x; 1.2173x over previous
#include <cuda_runtime.h>
#include <cuda_fp16.h>

#define NN    100000
#define FEAT  128
#define CLS   40
#define EMAX  1600000

// ---- scratch (static device globals; no allocation allowed) ----
__device__ int    g_degi[NN];
__device__ float  g_dinv[NN];
__device__ __half g_Hh[(size_t)NN * FEAT];   // pre-scaled fp16 messages h*dinv
__device__ float  g_AGG[(size_t)NN * FEAT];  // aggregation buffer
__device__ float  g_H2[(size_t)NN * CLS];    // last-layer GEMM output (fp32)
__device__ int    g_is64;                    // edge_index dtype flag
__device__ int    g_rowptr[NN + 1];
__device__ int    g_cursor[NN];
__device__ int    g_csr[EMAX];               // src ids grouped by dst
__device__ int    g_bsum[128];
__device__ int    g_boff[128];

// ---- mma helpers ----
__device__ __forceinline__ unsigned sm_u32(const void* p) {
    return (unsigned)__cvta_generic_to_shared(p);
}
__device__ __forceinline__ void ldm_x4(unsigned* r, unsigned a) {
    asm volatile("ldmatrix.sync.aligned.m8n8.x4.shared.b16 {%0,%1,%2,%3}, [%4];"
                 : "=r"(r[0]), "=r"(r[1]), "=r"(r[2]), "=r"(r[3]) : "r"(a));
}
__device__ __forceinline__ void ldm_x4t(unsigned* r, unsigned a) {
    asm volatile("ldmatrix.sync.aligned.m8n8.x4.trans.shared.b16 {%0,%1,%2,%3}, [%4];"
                 : "=r"(r[0]), "=r"(r[1]), "=r"(r[2]), "=r"(r[3]) : "r"(a));
}
__device__ __forceinline__ void mma16816(float* d, const unsigned* a,
                                         const unsigned* b) {
    asm volatile(
        "mma.sync.aligned.m16n8k16.row.col.f32.f16.f16.f32 "
        "{%0,%1,%2,%3},{%4,%5,%6,%7},{%8,%9},{%0,%1,%2,%3};"
        : "+f"(d[0]), "+f"(d[1]), "+f"(d[2]), "+f"(d[3])
        : "r"(a[0]), "r"(a[1]), "r"(a[2]), "r"(a[3]), "r"(b[0]), "r"(b[1]));
}

// ------------------------------------------------------------------
// degree / dinv / CSR build
// ------------------------------------------------------------------
__global__ void k_zero_deg(const void* ei, int n) {
    int i = blockIdx.x * blockDim.x + threadIdx.x;
    if (i < n) g_degi[i] = 0;
    if (i == 0) {
        const unsigned long long* p = (const unsigned long long*)ei;
        g_is64 = (p[0] < (unsigned long long)n && p[1] < (unsigned long long)n) ? 1 : 0;
    }
}

__global__ void k_count(const void* ei, int E) {
    int e = blockIdx.x * blockDim.x + threadIdx.x;
    if (e >= E) return;
    int dst;
    if (g_is64) dst = (int)((const long long*)ei)[E + e];
    else        dst = ((const int*)ei)[E + e];
    atomicAdd(&g_degi[dst], 1);
}

// scanA also produces dinv (fused)
__global__ void k_scanA(int n) {
    __shared__ int s[1024];
    int i = blockIdx.x * 1024 + threadIdx.x;
    int v = (i < n) ? g_degi[i] : 0;
    if (i < n) g_dinv[i] = rsqrtf((float)v + 1.f);
    s[threadIdx.x] = v;
    __syncthreads();
#pragma unroll
    for (int off = 1; off < 1024; off <<= 1) {
        int x = (threadIdx.x >= off) ? s[threadIdx.x - off] : 0;
        __syncthreads();
        s[threadIdx.x] += x;
        __syncthreads();
    }
    if (i < n) g_rowptr[i] = s[threadIdx.x] - v;
    if (threadIdx.x == 1023) g_bsum[blockIdx.x] = s[1023];
}

__global__ void k_scanB(int nb) {
    if (threadIdx.x == 0) {
        int acc = 0;
        for (int b = 0; b < nb; b++) { int t = g_bsum[b]; g_boff[b] = acc; acc += t; }
    }
}

__global__ void k_scanC(int n, int E) {
    int i = blockIdx.x * 1024 + threadIdx.x;
    if (i < n) {
        int r = g_rowptr[i] + g_boff[blockIdx.x];
        g_rowptr[i] = r;
        g_cursor[i] = r;
    }
    if (i == 0) g_rowptr[n] = E;
}

__global__ void k_fill(const void* ei, int E) {
    int e = blockIdx.x * blockDim.x + threadIdx.x;
    if (e >= E) return;
    int s, d;
    if (g_is64) {
        const long long* p = (const long long*)ei;
        s = (int)p[e]; d = (int)p[E + e];
    } else {
        const int* p = (const int*)ei;
        s = p[e]; d = p[E + e];
    }
    int pos = atomicAdd(&g_cursor[d], 1);
    g_csr[pos] = s;
}

// ------------------------------------------------------------------
// Tensor-core GEMM (K=128, Nout=128): h = act(A) @ W  (fp16 in, fp32 acc)
//   Hh  = half(h * dinv)    (pre-scaled message)
//   AGG = h * dinv^2 + b    (self-loop + bias, fp32)
// BM=128, BN=128, BK=64, 8 warps (4x2), warp tile 32x64, mma 16x8x16
// ------------------------------------------------------------------
template <bool RELU>
__global__ __launch_bounds__(256, 2)
void k_gemm128h(const float* __restrict__ A, const float* __restrict__ W,
                const float* __restrict__ b, __half* __restrict__ Hh,
                float* __restrict__ AGG, int n) {
    __shared__ __half As[128][72];   // [m][k], pad 8 -> 144B pitch (conflict-free ldmatrix)
    __shared__ __half Ws[64][136];   // [k][n], pad 8 -> 272B pitch
    const int tid  = threadIdx.x;
    const int lane = tid & 31;
    const int warp = tid >> 5;
    const int wm   = warp & 3;       // warp row: rows wm*32
    const int wn   = warp >> 2;      // warp col: cols wn*64
    const int row0 = blockIdx.x * 128;

    float acc[2][8][4];
#pragma unroll
    for (int mi = 0; mi < 2; mi++)
#pragma unroll
        for (int ni = 0; ni < 8; ni++)
#pragma unroll
            for (int q = 0; q < 4; q++) acc[mi][ni][q] = 0.f;

    const int ar = tid >> 1, ac = (tid & 1) * 32;   // A: 128 rows x 32 floats
    const int wr = tid >> 2, wc = (tid & 3) * 32;   // W: 64 rows x 32 floats

#pragma unroll
    for (int kb = 0; kb < 2; kb++) {
        if (kb) __syncthreads();
        // A tile -> fp16 smem (relu fused)
        {
            int gr = row0 + ar;
            const float* Arow = A + (size_t)gr * 128 + kb * 64 + ac;
#pragma unroll
            for (int u = 0; u < 4; u++) {
                float4 f0 = make_float4(0.f, 0.f, 0.f, 0.f), f1 = f0;
                if (gr < n) {
                    f0 = *(const float4*)(Arow + u * 8);
                    f1 = *(const float4*)(Arow + u * 8 + 4);
                }
                if (RELU) {
                    f0.x = fmaxf(f0.x, 0.f); f0.y = fmaxf(f0.y, 0.f);
                    f0.z = fmaxf(f0.z, 0.f); f0.w = fmaxf(f0.w, 0.f);
                    f1.x = fmaxf(f1.x, 0.f); f1.y = fmaxf(f1.y, 0.f);
                    f1.z = fmaxf(f1.z, 0.f); f1.w = fmaxf(f1.w, 0.f);
                }
                __half2 hh[4];
                hh[0] = __floats2half2_rn(f0.x, f0.y);
                hh[1] = __floats2half2_rn(f0.z, f0.w);
                hh[2] = __floats2half2_rn(f1.x, f1.y);
                hh[3] = __floats2half2_rn(f1.z, f1.w);
                *(uint4*)&As[ar][ac + u * 8] = *(uint4*)hh;
            }
        }
        // W tile -> fp16 smem
        {
            const float* Wrow = W + (size_t)(kb * 64 + wr) * 128 + wc;
#pragma unroll
            for (int u = 0; u < 4; u++) {
                float4 f0 = *(const float4*)(Wrow + u * 8);
                float4 f1 = *(const float4*)(Wrow + u * 8 + 4);
                __half2 hh[4];
                hh[0] = __floats2half2_rn(f0.x, f0.y);
                hh[1] = __floats2half2_rn(f0.z, f0.w);
                hh[2] = __floats2half2_rn(f1.x, f1.y);
                hh[3] = __floats2half2_rn(f1.z, f1.w);
                *(uint4*)&Ws[wr][wc + u * 8] = *(uint4*)hh;
            }
        }
        __syncthreads();

#pragma unroll
        for (int kk = 0; kk < 4; kk++) {
            unsigned af[2][4];
#pragma unroll
            for (int mi = 0; mi < 2; mi++) {
                int r = wm * 32 + mi * 16 + (lane & 15);
                int kh = kk * 16 + (lane >> 4) * 8;
                ldm_x4(af[mi], sm_u32(&As[r][kh]));
            }
            unsigned bf[8][2];
#pragma unroll
            for (int nt = 0; nt < 4; nt++) {   // two n-tiles per ldmatrix.x4.trans
                int g = lane >> 3, r = lane & 7;
                int krow = kk * 16 + (g & 1) * 8 + r;
                int ncol = wn * 64 + nt * 16 + (g >> 1) * 8;
                unsigned t[4];
                ldm_x4t(t, sm_u32(&Ws[krow][ncol]));
                bf[nt * 2 + 0][0] = t[0]; bf[nt * 2 + 0][1] = t[1];
                bf[nt * 2 + 1][0] = t[2]; bf[nt * 2 + 1][1] = t[3];
            }
#pragma unroll
            for (int mi = 0; mi < 2; mi++)
#pragma unroll
                for (int ni = 0; ni < 8; ni++)
                    mma16816(acc[mi][ni], af[mi], bf[ni]);
        }
    }

    // epilogue
    const int r1 = lane >> 2;
    const int c2 = (lane & 3) * 2;
    float2 bias2[8];
#pragma unroll
    for (int ni = 0; ni < 8; ni++) {
        int col = wn * 64 + ni * 8 + c2;
        bias2[ni] = *(const float2*)(b + col);
    }
#pragma unroll
    for (int mi = 0; mi < 2; mi++) {
        int gr0 = row0 + wm * 32 + mi * 16 + r1;
        int gr1 = gr0 + 8;
        float d0 = (gr0 < n) ? g_dinv[gr0] : 0.f;
        float d1 = (gr1 < n) ? g_dinv[gr1] : 0.f;
        float dd0 = d0 * d0, dd1 = d1 * d1;
#pragma unroll
        for (int ni = 0; ni < 8; ni++) {
            int col = wn * 64 + ni * 8 + c2;
            float c0 = acc[mi][ni][0], c1 = acc[mi][ni][1];
            float c3 = acc[mi][ni][2], c4 = acc[mi][ni][3];
            if (gr0 < n) {
                __half2 h = __floats2half2_rn(c0 * d0, c1 * d0);
                *(unsigned*)(Hh + (size_t)gr0 * 128 + col) = *(unsigned*)&h;
                float2 g = make_float2(c0 * dd0 + bias2[ni].x, c1 * dd0 + bias2[ni].y);
                *(float2*)(AGG + (size_t)gr0 * 128 + col) = g;
            }
            if (gr1 < n) {
                __half2 h = __floats2half2_rn(c3 * d1, c4 * d1);
                *(unsigned*)(Hh + (size_t)gr1 * 128 + col) = *(unsigned*)&h;
                float2 g = make_float2(c3 * dd1 + bias2[ni].x, c4 * dd1 + bias2[ni].y);
                *(float2*)(AGG + (size_t)gr1 * 128 + col) = g;
            }
        }
    }
}

// ------------------------------------------------------------------
// GEMM (K=128, Nout=40): H2 = relu(A) @ W2 ; OUT = H2 * dinv^2 + b2 (fp32)
// ------------------------------------------------------------------
template <bool RELU>
__global__ __launch_bounds__(256)
void k_gemm40(const float* __restrict__ A, const float* __restrict__ W,
              const float* __restrict__ b, float* __restrict__ H2,
              float* __restrict__ OUT, int n) {
    __shared__ float As[16][128];
    __shared__ float Ws[128][40];
    const int tid = threadIdx.x;
    const int tx = tid & 7;
    const int ty = tid >> 3;
    const int row0 = blockIdx.x * 128;
    const int ar = tid >> 2;
    const int ac = tid & 3;

    for (int idx = tid; idx < 128 * 40; idx += 256)
        Ws[idx / 40][idx % 40] = W[idx];

    float acc[4][5];
#pragma unroll
    for (int i = 0; i < 4; i++)
#pragma unroll
        for (int j = 0; j < 5; j++) acc[i][j] = 0.f;

    for (int k0 = 0; k0 < 128; k0 += 16) {
        float4 av4[2];
#pragma unroll
        for (int l = 0; l < 2; l++) {
            int gr = row0 + ar + l * 64;
            float4 a = make_float4(0.f, 0.f, 0.f, 0.f);
            if (gr < n) a = *(const float4*)(A + (size_t)gr * 128 + k0 + ac * 4);
            if (RELU) {
                a.x = fmaxf(a.x, 0.f); a.y = fmaxf(a.y, 0.f);
                a.z = fmaxf(a.z, 0.f); a.w = fmaxf(a.w, 0.f);
            }
            av4[l] = a;
        }
        __syncthreads();
#pragma unroll
        for (int l = 0; l < 2; l++) {
            int r = ar + l * 64;
            As[ac * 4 + 0][r] = av4[l].x;
            As[ac * 4 + 1][r] = av4[l].y;
            As[ac * 4 + 2][r] = av4[l].z;
            As[ac * 4 + 3][r] = av4[l].w;
        }
        __syncthreads();
#pragma unroll
        for (int k = 0; k < 16; k++) {
            float4 a0 = *(const float4*)&As[k][ty * 4];
            float av[4] = {a0.x, a0.y, a0.z, a0.w};
            float wv[5];
#pragma unroll
            for (int j = 0; j < 5; j++) wv[j] = Ws[k0 + k][tx * 5 + j];
#pragma unroll
            for (int i = 0; i < 4; i++)
#pragma unroll
                for (int j = 0; j < 5; j++) acc[i][j] += av[i] * wv[j];
        }
        __syncthreads();
    }

#pragma unroll
    for (int i = 0; i < 4; i++) {
        int gr = row0 + ty * 4 + i;
        if (gr >= n) continue;
        float di = g_dinv[gr];
        float dd = di * di;
#pragma unroll
        for (int j = 0; j < 5; j++) {
            int c = tx * 5 + j;
            float h = acc[i][j];
            H2[(size_t)gr * 40 + c]  = h;
            OUT[(size_t)gr * 40 + c] = h * dd + b[c];
        }
    }
}

// ------------------------------------------------------------------
// SpMM aggregation (fp16 pre-scaled messages):
//   AGG[d] += dinv[d] * sum_{s in row d} Hh[s]
// ------------------------------------------------------------------
__global__ __launch_bounds__(256)
void k_spmm128(const __half* __restrict__ hh, float* __restrict__ agg, int n) {
    int w = (blockIdx.x * blockDim.x + threadIdx.x) >> 5;
    if (w >= n) return;
    int lane = threadIdx.x & 31;
    int beg = g_rowptr[w];
    int end = g_rowptr[w + 1];
    float dd = g_dinv[w];
    float4 acc = make_float4(0.f, 0.f, 0.f, 0.f);

    int idx = beg;
    for (; idx + 4 <= end; idx += 4) {
        int s0 = g_csr[idx + 0], s1 = g_csr[idx + 1];
        int s2 = g_csr[idx + 2], s3 = g_csr[idx + 3];
        uint2 u0 = *(const uint2*)(hh + (size_t)s0 * 128 + lane * 4);
        uint2 u1 = *(const uint2*)(hh + (size_t)s1 * 128 + lane * 4);
        uint2 u2 = *(const uint2*)(hh + (size_t)s2 * 128 + lane * 4);
        uint2 u3 = *(const uint2*)(hh + (size_t)s3 * 128 + lane * 4);
#pragma unroll
        for (int q = 0; q < 4; q++) {
            uint2 u = (q == 0) ? u0 : (q == 1) ? u1 : (q == 2) ? u2 : u3;
            float2 f0 = __half22float2(*(const __half2*)&u.x);
            float2 f1 = __half22float2(*(const __half2*)&u.y);
            acc.x += f0.x; acc.y += f0.y; acc.z += f1.x; acc.w += f1.y;
        }
    }
    for (; idx < end; ++idx) {
        int s = g_csr[idx];
        uint2 u = *(const uint2*)(hh + (size_t)s * 128 + lane * 4);
        float2 f0 = __half22float2(*(const __half2*)&u.x);
        float2 f1 = __half22float2(*(const __half2*)&u.y);
        acc.x += f0.x; acc.y += f0.y; acc.z += f1.x; acc.w += f1.y;
    }
    float* o = agg + (size_t)w * 128 + lane * 4;
    float4 cur = *(const float4*)o;
    cur.x += dd * acc.x; cur.y += dd * acc.y;
    cur.z += dd * acc.z; cur.w += dd * acc.w;
    *(float4*)o = cur;
}

__global__ __launch_bounds__(256)
void k_spmm40(const float* __restrict__ h, float* __restrict__ out, int n) {
    int w = (blockIdx.x * blockDim.x + threadIdx.x) >> 5;
    if (w >= n) return;
    int lane = threadIdx.x & 31;
    if (lane >= 20) return;
    int beg = g_rowptr[w];
    int end = g_rowptr[w + 1];
    float dd = g_dinv[w];
    float2 acc = make_float2(0.f, 0.f);

    int idx = beg;
    for (; idx + 4 <= end; idx += 4) {
        int s0 = g_csr[idx + 0], s1 = g_csr[idx + 1];
        int s2 = g_csr[idx + 2], s3 = g_csr[idx + 3];
        float n0 = g_dinv[s0], n1 = g_dinv[s1];
        float n2 = g_dinv[s2], n3 = g_dinv[s3];
        float2 v0 = *(const float2*)(h + (size_t)s0 * 40 + lane * 2);
        float2 v1 = *(const float2*)(h + (size_t)s1 * 40 + lane * 2);
        float2 v2 = *(const float2*)(h + (size_t)s2 * 40 + lane * 2);
        float2 v3 = *(const float2*)(h + (size_t)s3 * 40 + lane * 2);
        acc.x += n0 * v0.x; acc.y += n0 * v0.y;
        acc.x += n1 * v1.x; acc.y += n1 * v1.y;
        acc.x += n2 * v2.x; acc.y += n2 * v2.y;
        acc.x += n3 * v3.x; acc.y += n3 * v3.y;
    }
    for (; idx < end; ++idx) {
        int s = g_csr[idx];
        float nr = g_dinv[s];
        float2 v = *(const float2*)(h + (size_t)s * 40 + lane * 2);
        acc.x += nr * v.x; acc.y += nr * v.y;
    }
    float* o = out + (size_t)w * 40 + lane * 2;
    float2 cur = *(const float2*)o;
    cur.x += dd * acc.x; cur.y += dd * acc.y;
    *(float2*)o = cur;
}

// ------------------------------------------------------------------
extern "C" void kernel_launch(void* const* d_in, const int* in_sizes, int n_in,
                              void* d_out, int out_size) {
    const float* x  = (const float*)d_in[0];
    const float* W0 = (const float*)d_in[1];
    const float* b0 = (const float*)d_in[2];
    const float* W1 = (const float*)d_in[3];
    const float* b1 = (const float*)d_in[4];
    const float* W2 = (const float*)d_in[5];
    const float* b2 = (const float*)d_in[6];
    const void*  ei = d_in[7];
    int n = in_sizes[0] / FEAT;
    int E = in_sizes[7] / 2;
    if (E > EMAX) E = EMAX;
    float* out = (float*)d_out;

    __half* pHh; float *pAGG, *pH2;
    cudaGetSymbolAddress((void**)&pHh,  g_Hh);
    cudaGetSymbolAddress((void**)&pAGG, g_AGG);
    cudaGetSymbolAddress((void**)&pH2,  g_H2);

    const int tb = 256;
    int nblk  = (n + tb - 1) / tb;
    int eblk  = (E + tb - 1) / tb;
    int gblk  = (n + 127) / 128;
    int scblk = (n + 1023) / 1024;
    int wblk  = (int)(((long long)n * 32 + tb - 1) / tb);

    // degree + CSR build
    k_zero_deg<<<nblk, tb>>>(ei, n);
    k_count<<<eblk, tb>>>(ei, E);
    k_scanA<<<scblk, 1024>>>(n);
    k_scanB<<<1, 32>>>(scblk);
    k_scanC<<<scblk, 1024>>>(n, E);
    k_fill<<<eblk, tb>>>(ei, E);

    // layer 0
    k_gemm128h<false><<<gblk, 256>>>(x, W0, b0, pHh, pAGG, n);
    k_spmm128<<<wblk, tb>>>(pHh, pAGG, n);
    // layer 1 (ReLU fused into next GEMM's A-load)
    k_gemm128h<true><<<gblk, 256>>>(pAGG, W1, b1, pHh, pAGG, n);
    k_spmm128<<<wblk, tb>>>(pHh, pAGG, n);
    // layer 2 (fp32 for final precision)
    k_gemm40<true><<<gblk, 256>>>(pAGG, W2, b2, pH2, out, n);
    k_spmm40<<<wblk, tb>>>(pH2, out, n);
}

// round 6
// speedup vs baseline: 4.7050x; 1.1181x over previous
#include <cuda_runtime.h>
#include <cuda_fp16.h>

#define NN    100000
#define FEAT  128
#define CLS   40
#define EMAX  1600000

// ---- scratch (static device globals; no allocation allowed) ----
__device__ int    g_degi[NN];
__device__ float  g_dinv[NN];
__device__ __half g_Hh[(size_t)NN * FEAT];   // pre-scaled fp16 messages h*dinv
__device__ float  g_AGG[(size_t)NN * FEAT];  // aggregation buffer
__device__ __half g_H2h[(size_t)NN * CLS];   // layer-2 pre-scaled fp16 messages
__device__ int    g_is64;                    // edge_index dtype flag
__device__ int    g_rowptr[NN + 1];
__device__ int    g_cursor[NN];
__device__ int    g_csr[EMAX];               // src ids grouped by dst
__device__ int    g_bsum[128];
__device__ int    g_boff[128];

// ---- mma helpers ----
__device__ __forceinline__ unsigned sm_u32(const void* p) {
    return (unsigned)__cvta_generic_to_shared(p);
}
__device__ __forceinline__ void ldm_x4(unsigned* r, unsigned a) {
    asm volatile("ldmatrix.sync.aligned.m8n8.x4.shared.b16 {%0,%1,%2,%3}, [%4];"
                 : "=r"(r[0]), "=r"(r[1]), "=r"(r[2]), "=r"(r[3]) : "r"(a));
}
__device__ __forceinline__ void ldm_x4t(unsigned* r, unsigned a) {
    asm volatile("ldmatrix.sync.aligned.m8n8.x4.trans.shared.b16 {%0,%1,%2,%3}, [%4];"
                 : "=r"(r[0]), "=r"(r[1]), "=r"(r[2]), "=r"(r[3]) : "r"(a));
}
__device__ __forceinline__ void mma16816(float* d, const unsigned* a,
                                         const unsigned* b) {
    asm volatile(
        "mma.sync.aligned.m16n8k16.row.col.f32.f16.f16.f32 "
        "{%0,%1,%2,%3},{%4,%5,%6,%7},{%8,%9},{%0,%1,%2,%3};"
        : "+f"(d[0]), "+f"(d[1]), "+f"(d[2]), "+f"(d[3])
        : "r"(a[0]), "r"(a[1]), "r"(a[2]), "r"(a[3]), "r"(b[0]), "r"(b[1]));
}

// ------------------------------------------------------------------
// degree / dinv / CSR build
// ------------------------------------------------------------------
__global__ void k_zero_deg(const void* ei, int n) {
    int i = blockIdx.x * blockDim.x + threadIdx.x;
    if (i < n) g_degi[i] = 0;
    if (i == 0) {
        const unsigned long long* p = (const unsigned long long*)ei;
        g_is64 = (p[0] < (unsigned long long)n && p[1] < (unsigned long long)n) ? 1 : 0;
    }
}

__global__ void k_count(const void* ei, int E) {
    int e = blockIdx.x * blockDim.x + threadIdx.x;
    if (e >= E) return;
    int dst;
    if (g_is64) dst = (int)((const long long*)ei)[E + e];
    else        dst = ((const int*)ei)[E + e];
    atomicAdd(&g_degi[dst], 1);
}

// scanA also produces dinv (fused)
__global__ void k_scanA(int n) {
    __shared__ int s[1024];
    int i = blockIdx.x * 1024 + threadIdx.x;
    int v = (i < n) ? g_degi[i] : 0;
    if (i < n) g_dinv[i] = rsqrtf((float)v + 1.f);
    s[threadIdx.x] = v;
    __syncthreads();
#pragma unroll
    for (int off = 1; off < 1024; off <<= 1) {
        int x = (threadIdx.x >= off) ? s[threadIdx.x - off] : 0;
        __syncthreads();
        s[threadIdx.x] += x;
        __syncthreads();
    }
    if (i < n) g_rowptr[i] = s[threadIdx.x] - v;
    if (threadIdx.x == 1023) g_bsum[blockIdx.x] = s[1023];
}

// parallel exclusive scan of <=128 block sums (one block, 128 threads)
__global__ void k_scanB(int nb) {
    __shared__ int s[128];
    int t = threadIdx.x;
    int v = (t < nb) ? g_bsum[t] : 0;
    s[t] = v;
    __syncthreads();
#pragma unroll
    for (int off = 1; off < 128; off <<= 1) {
        int x = (t >= off) ? s[t - off] : 0;
        __syncthreads();
        s[t] += x;
        __syncthreads();
    }
    g_boff[t] = s[t] - v;
}

__global__ void k_scanC(int n, int E) {
    int i = blockIdx.x * 1024 + threadIdx.x;
    if (i < n) {
        int r = g_rowptr[i] + g_boff[blockIdx.x];
        g_rowptr[i] = r;
        g_cursor[i] = r;
    }
    if (i == 0) g_rowptr[n] = E;
}

__global__ void k_fill(const void* ei, int E) {
    int e = blockIdx.x * blockDim.x + threadIdx.x;
    if (e >= E) return;
    int s, d;
    if (g_is64) {
        const long long* p = (const long long*)ei;
        s = (int)p[e]; d = (int)p[E + e];
    } else {
        const int* p = (const int*)ei;
        s = p[e]; d = p[E + e];
    }
    int pos = atomicAdd(&g_cursor[d], 1);
    g_csr[pos] = s;
}

// ------------------------------------------------------------------
// Tensor-core GEMM (K=128, Nout=128): h = act(A) @ W  (fp16 in, fp32 acc)
//   Hh  = half(h * dinv)    (pre-scaled message)
//   AGG = h * dinv^2 + b    (self-loop + bias, fp32)
// BM=128, BN=128, BK=64, 8 warps (4x2), warp tile 32x64, mma 16x8x16
// ------------------------------------------------------------------
template <bool RELU>
__global__ __launch_bounds__(256, 2)
void k_gemm128h(const float* __restrict__ A, const float* __restrict__ W,
                const float* __restrict__ b, __half* __restrict__ Hh,
                float* __restrict__ AGG, int n) {
    __shared__ __half As[128][72];   // [m][k], pad 8 -> conflict-free ldmatrix
    __shared__ __half Ws[64][136];   // [k][n], pad 8
    const int tid  = threadIdx.x;
    const int lane = tid & 31;
    const int warp = tid >> 5;
    const int wm   = warp & 3;
    const int wn   = warp >> 2;
    const int row0 = blockIdx.x * 128;

    float acc[2][8][4];
#pragma unroll
    for (int mi = 0; mi < 2; mi++)
#pragma unroll
        for (int ni = 0; ni < 8; ni++)
#pragma unroll
            for (int q = 0; q < 4; q++) acc[mi][ni][q] = 0.f;

    const int ar = tid >> 1, ac = (tid & 1) * 32;
    const int wr = tid >> 2, wc = (tid & 3) * 32;

#pragma unroll
    for (int kb = 0; kb < 2; kb++) {
        if (kb) __syncthreads();
        {
            int gr = row0 + ar;
            const float* Arow = A + (size_t)gr * 128 + kb * 64 + ac;
#pragma unroll
            for (int u = 0; u < 4; u++) {
                float4 f0 = make_float4(0.f, 0.f, 0.f, 0.f), f1 = f0;
                if (gr < n) {
                    f0 = *(const float4*)(Arow + u * 8);
                    f1 = *(const float4*)(Arow + u * 8 + 4);
                }
                if (RELU) {
                    f0.x = fmaxf(f0.x, 0.f); f0.y = fmaxf(f0.y, 0.f);
                    f0.z = fmaxf(f0.z, 0.f); f0.w = fmaxf(f0.w, 0.f);
                    f1.x = fmaxf(f1.x, 0.f); f1.y = fmaxf(f1.y, 0.f);
                    f1.z = fmaxf(f1.z, 0.f); f1.w = fmaxf(f1.w, 0.f);
                }
                __half2 hh[4];
                hh[0] = __floats2half2_rn(f0.x, f0.y);
                hh[1] = __floats2half2_rn(f0.z, f0.w);
                hh[2] = __floats2half2_rn(f1.x, f1.y);
                hh[3] = __floats2half2_rn(f1.z, f1.w);
                *(uint4*)&As[ar][ac + u * 8] = *(uint4*)hh;
            }
        }
        {
            const float* Wrow = W + (size_t)(kb * 64 + wr) * 128 + wc;
#pragma unroll
            for (int u = 0; u < 4; u++) {
                float4 f0 = *(const float4*)(Wrow + u * 8);
                float4 f1 = *(const float4*)(Wrow + u * 8 + 4);
                __half2 hh[4];
                hh[0] = __floats2half2_rn(f0.x, f0.y);
                hh[1] = __floats2half2_rn(f0.z, f0.w);
                hh[2] = __floats2half2_rn(f1.x, f1.y);
                hh[3] = __floats2half2_rn(f1.z, f1.w);
                *(uint4*)&Ws[wr][wc + u * 8] = *(uint4*)hh;
            }
        }
        __syncthreads();

#pragma unroll
        for (int kk = 0; kk < 4; kk++) {
            unsigned af[2][4];
#pragma unroll
            for (int mi = 0; mi < 2; mi++) {
                int r = wm * 32 + mi * 16 + (lane & 15);
                int kh = kk * 16 + (lane >> 4) * 8;
                ldm_x4(af[mi], sm_u32(&As[r][kh]));
            }
            unsigned bf[8][2];
#pragma unroll
            for (int nt = 0; nt < 4; nt++) {
                int g = lane >> 3, r = lane & 7;
                int krow = kk * 16 + (g & 1) * 8 + r;
                int ncol = wn * 64 + nt * 16 + (g >> 1) * 8;
                unsigned t[4];
                ldm_x4t(t, sm_u32(&Ws[krow][ncol]));
                bf[nt * 2 + 0][0] = t[0]; bf[nt * 2 + 0][1] = t[1];
                bf[nt * 2 + 1][0] = t[2]; bf[nt * 2 + 1][1] = t[3];
            }
#pragma unroll
            for (int mi = 0; mi < 2; mi++)
#pragma unroll
                for (int ni = 0; ni < 8; ni++)
                    mma16816(acc[mi][ni], af[mi], bf[ni]);
        }
    }

    const int r1 = lane >> 2;
    const int c2 = (lane & 3) * 2;
    float2 bias2[8];
#pragma unroll
    for (int ni = 0; ni < 8; ni++)
        bias2[ni] = *(const float2*)(b + wn * 64 + ni * 8 + c2);
#pragma unroll
    for (int mi = 0; mi < 2; mi++) {
        int gr0 = row0 + wm * 32 + mi * 16 + r1;
        int gr1 = gr0 + 8;
        float d0 = (gr0 < n) ? g_dinv[gr0] : 0.f;
        float d1 = (gr1 < n) ? g_dinv[gr1] : 0.f;
        float dd0 = d0 * d0, dd1 = d1 * d1;
#pragma unroll
        for (int ni = 0; ni < 8; ni++) {
            int col = wn * 64 + ni * 8 + c2;
            float c0 = acc[mi][ni][0], c1 = acc[mi][ni][1];
            float c3 = acc[mi][ni][2], c4 = acc[mi][ni][3];
            if (gr0 < n) {
                __half2 h = __floats2half2_rn(c0 * d0, c1 * d0);
                *(unsigned*)(Hh + (size_t)gr0 * 128 + col) = *(unsigned*)&h;
                float2 g = make_float2(c0 * dd0 + bias2[ni].x, c1 * dd0 + bias2[ni].y);
                *(float2*)(AGG + (size_t)gr0 * 128 + col) = g;
            }
            if (gr1 < n) {
                __half2 h = __floats2half2_rn(c3 * d1, c4 * d1);
                *(unsigned*)(Hh + (size_t)gr1 * 128 + col) = *(unsigned*)&h;
                float2 g = make_float2(c3 * dd1 + bias2[ni].x, c4 * dd1 + bias2[ni].y);
                *(float2*)(AGG + (size_t)gr1 * 128 + col) = g;
            }
        }
    }
}

// ------------------------------------------------------------------
// Tensor-core GEMM (K=128, Nout=40 padded to 64):
//   h2  = relu(A) @ W2
//   H2h = half(h2 * dinv) ; OUT = h2 * dinv^2 + b2 (fp32)
// BM=128, BN=64, BK=64, 8 warps (4x2), warp tile 32x32
// ------------------------------------------------------------------
__global__ __launch_bounds__(256, 2)
void k_gemm40h(const float* __restrict__ A, const float* __restrict__ W,
               const float* __restrict__ b, __half* __restrict__ H2h,
               float* __restrict__ OUT, int n) {
    __shared__ __half As[128][72];   // [m][k-block]
    __shared__ __half Ws[64][72];    // [k][n] 64 cols (40 real, rest 0)
    const int tid  = threadIdx.x;
    const int lane = tid & 31;
    const int warp = tid >> 5;
    const int wm   = warp & 3;
    const int wn   = warp >> 2;
    const int row0 = blockIdx.x * 128;

    float acc[2][4][4];
#pragma unroll
    for (int mi = 0; mi < 2; mi++)
#pragma unroll
        for (int ni = 0; ni < 4; ni++)
#pragma unroll
            for (int q = 0; q < 4; q++) acc[mi][ni][q] = 0.f;

    const int ar = tid >> 1, ac = (tid & 1) * 32;

#pragma unroll
    for (int kb = 0; kb < 2; kb++) {
        if (kb) __syncthreads();
        // A tile (relu fused)
        {
            int gr = row0 + ar;
            const float* Arow = A + (size_t)gr * 128 + kb * 64 + ac;
#pragma unroll
            for (int u = 0; u < 4; u++) {
                float4 f0 = make_float4(0.f, 0.f, 0.f, 0.f), f1 = f0;
                if (gr < n) {
                    f0 = *(const float4*)(Arow + u * 8);
                    f1 = *(const float4*)(Arow + u * 8 + 4);
                }
                f0.x = fmaxf(f0.x, 0.f); f0.y = fmaxf(f0.y, 0.f);
                f0.z = fmaxf(f0.z, 0.f); f0.w = fmaxf(f0.w, 0.f);
                f1.x = fmaxf(f1.x, 0.f); f1.y = fmaxf(f1.y, 0.f);
                f1.z = fmaxf(f1.z, 0.f); f1.w = fmaxf(f1.w, 0.f);
                __half2 hh[4];
                hh[0] = __floats2half2_rn(f0.x, f0.y);
                hh[1] = __floats2half2_rn(f0.z, f0.w);
                hh[2] = __floats2half2_rn(f1.x, f1.y);
                hh[3] = __floats2half2_rn(f1.z, f1.w);
                *(uint4*)&As[ar][ac + u * 8] = *(uint4*)hh;
            }
        }
        // W tile: 64 k-rows x 64 cols (40 real)
        for (int idx = tid; idx < 64 * 64; idx += 256) {
            int k = idx >> 6, c = idx & 63;
            float v = (c < 40) ? W[(size_t)(kb * 64 + k) * 40 + c] : 0.f;
            Ws[k][c] = __float2half_rn(v);
        }
        __syncthreads();

#pragma unroll
        for (int kk = 0; kk < 4; kk++) {
            unsigned af[2][4];
#pragma unroll
            for (int mi = 0; mi < 2; mi++) {
                int r = wm * 32 + mi * 16 + (lane & 15);
                int kh = kk * 16 + (lane >> 4) * 8;
                ldm_x4(af[mi], sm_u32(&As[r][kh]));
            }
            unsigned bf[4][2];
#pragma unroll
            for (int nt = 0; nt < 2; nt++) {
                int g = lane >> 3, r = lane & 7;
                int krow = kk * 16 + (g & 1) * 8 + r;
                int ncol = wn * 32 + nt * 16 + (g >> 1) * 8;
                unsigned t[4];
                ldm_x4t(t, sm_u32(&Ws[krow][ncol]));
                bf[nt * 2 + 0][0] = t[0]; bf[nt * 2 + 0][1] = t[1];
                bf[nt * 2 + 1][0] = t[2]; bf[nt * 2 + 1][1] = t[3];
            }
#pragma unroll
            for (int mi = 0; mi < 2; mi++)
#pragma unroll
                for (int ni = 0; ni < 4; ni++)
                    mma16816(acc[mi][ni], af[mi], bf[ni]);
        }
    }

    const int r1 = lane >> 2;
    const int c2 = (lane & 3) * 2;
#pragma unroll
    for (int mi = 0; mi < 2; mi++) {
        int gr0 = row0 + wm * 32 + mi * 16 + r1;
        int gr1 = gr0 + 8;
        float d0 = (gr0 < n) ? g_dinv[gr0] : 0.f;
        float d1 = (gr1 < n) ? g_dinv[gr1] : 0.f;
        float dd0 = d0 * d0, dd1 = d1 * d1;
#pragma unroll
        for (int ni = 0; ni < 4; ni++) {
            int col = wn * 32 + ni * 8 + c2;
            if (col >= 40) continue;
            float bx = b[col], by = b[col + 1];
            float c0 = acc[mi][ni][0], c1 = acc[mi][ni][1];
            float c3 = acc[mi][ni][2], c4 = acc[mi][ni][3];
            if (gr0 < n) {
                __half2 h = __floats2half2_rn(c0 * d0, c1 * d0);
                *(unsigned*)(H2h + (size_t)gr0 * 40 + col) = *(unsigned*)&h;
                *(float2*)(OUT + (size_t)gr0 * 40 + col) =
                    make_float2(c0 * dd0 + bx, c1 * dd0 + by);
            }
            if (gr1 < n) {
                __half2 h = __floats2half2_rn(c3 * d1, c4 * d1);
                *(unsigned*)(H2h + (size_t)gr1 * 40 + col) = *(unsigned*)&h;
                *(float2*)(OUT + (size_t)gr1 * 40 + col) =
                    make_float2(c3 * dd1 + bx, c4 * dd1 + by);
            }
        }
    }
}

// ------------------------------------------------------------------
// SpMM aggregation (fp16 pre-scaled messages):
//   AGG[d] += dinv[d] * sum_{s in row d} Hh[s]
// ------------------------------------------------------------------
__global__ __launch_bounds__(256)
void k_spmm128(const __half* __restrict__ hh, float* __restrict__ agg, int n) {
    int w = (blockIdx.x * blockDim.x + threadIdx.x) >> 5;
    if (w >= n) return;
    int lane = threadIdx.x & 31;
    int beg = g_rowptr[w];
    int end = g_rowptr[w + 1];
    float dd = g_dinv[w];
    float4 acc = make_float4(0.f, 0.f, 0.f, 0.f);

    int idx = beg;
    for (; idx + 4 <= end; idx += 4) {
        int s0 = g_csr[idx + 0], s1 = g_csr[idx + 1];
        int s2 = g_csr[idx + 2], s3 = g_csr[idx + 3];
        uint2 u0 = *(const uint2*)(hh + (size_t)s0 * 128 + lane * 4);
        uint2 u1 = *(const uint2*)(hh + (size_t)s1 * 128 + lane * 4);
        uint2 u2 = *(const uint2*)(hh + (size_t)s2 * 128 + lane * 4);
        uint2 u3 = *(const uint2*)(hh + (size_t)s3 * 128 + lane * 4);
#pragma unroll
        for (int q = 0; q < 4; q++) {
            uint2 u = (q == 0) ? u0 : (q == 1) ? u1 : (q == 2) ? u2 : u3;
            float2 f0 = __half22float2(*(const __half2*)&u.x);
            float2 f1 = __half22float2(*(const __half2*)&u.y);
            acc.x += f0.x; acc.y += f0.y; acc.z += f1.x; acc.w += f1.y;
        }
    }
    for (; idx < end; ++idx) {
        int s = g_csr[idx];
        uint2 u = *(const uint2*)(hh + (size_t)s * 128 + lane * 4);
        float2 f0 = __half22float2(*(const __half2*)&u.x);
        float2 f1 = __half22float2(*(const __half2*)&u.y);
        acc.x += f0.x; acc.y += f0.y; acc.z += f1.x; acc.w += f1.y;
    }
    float* o = agg + (size_t)w * 128 + lane * 4;
    float4 cur = *(const float4*)o;
    cur.x += dd * acc.x; cur.y += dd * acc.y;
    cur.z += dd * acc.z; cur.w += dd * acc.w;
    *(float4*)o = cur;
}

// layer-2 spmm on fp16 pre-scaled messages (20 lanes x 2 cols)
__global__ __launch_bounds__(256)
void k_spmm40h(const __half* __restrict__ hh, float* __restrict__ out, int n) {
    int w = (blockIdx.x * blockDim.x + threadIdx.x) >> 5;
    if (w >= n) return;
    int lane = threadIdx.x & 31;
    if (lane >= 20) return;
    int beg = g_rowptr[w];
    int end = g_rowptr[w + 1];
    float dd = g_dinv[w];
    float2 acc = make_float2(0.f, 0.f);

    int idx = beg;
    for (; idx + 4 <= end; idx += 4) {
        int s0 = g_csr[idx + 0], s1 = g_csr[idx + 1];
        int s2 = g_csr[idx + 2], s3 = g_csr[idx + 3];
        unsigned u0 = *(const unsigned*)(hh + (size_t)s0 * 40 + lane * 2);
        unsigned u1 = *(const unsigned*)(hh + (size_t)s1 * 40 + lane * 2);
        unsigned u2 = *(const unsigned*)(hh + (size_t)s2 * 40 + lane * 2);
        unsigned u3 = *(const unsigned*)(hh + (size_t)s3 * 40 + lane * 2);
        float2 f0 = __half22float2(*(const __half2*)&u0);
        float2 f1 = __half22float2(*(const __half2*)&u1);
        float2 f2 = __half22float2(*(const __half2*)&u2);
        float2 f3 = __half22float2(*(const __half2*)&u3);
        acc.x += f0.x + f1.x + f2.x + f3.x;
        acc.y += f0.y + f1.y + f2.y + f3.y;
    }
    for (; idx < end; ++idx) {
        int s = g_csr[idx];
        unsigned u = *(const unsigned*)(hh + (size_t)s * 40 + lane * 2);
        float2 f = __half22float2(*(const __half2*)&u);
        acc.x += f.x; acc.y += f.y;
    }
    float* o = out + (size_t)w * 40 + lane * 2;
    float2 cur = *(const float2*)o;
    cur.x += dd * acc.x; cur.y += dd * acc.y;
    *(float2*)o = cur;
}

// ------------------------------------------------------------------
extern "C" void kernel_launch(void* const* d_in, const int* in_sizes, int n_in,
                              void* d_out, int out_size) {
    const float* x  = (const float*)d_in[0];
    const float* W0 = (const float*)d_in[1];
    const float* b0 = (const float*)d_in[2];
    const float* W1 = (const float*)d_in[3];
    const float* b1 = (const float*)d_in[4];
    const float* W2 = (const float*)d_in[5];
    const float* b2 = (const float*)d_in[6];
    const void*  ei = d_in[7];
    int n = in_sizes[0] / FEAT;
    int E = in_sizes[7] / 2;
    if (E > EMAX) E = EMAX;
    float* out = (float*)d_out;

    __half *pHh, *pH2h; float* pAGG;
    cudaGetSymbolAddress((void**)&pHh,  g_Hh);
    cudaGetSymbolAddress((void**)&pH2h, g_H2h);
    cudaGetSymbolAddress((void**)&pAGG, g_AGG);

    const int tb = 256;
    int nblk  = (n + tb - 1) / tb;
    int eblk  = (E + tb - 1) / tb;
    int gblk  = (n + 127) / 128;
    int scblk = (n + 1023) / 1024;
    int wblk  = (int)(((long long)n * 32 + tb - 1) / tb);

    // degree + CSR build
    k_zero_deg<<<nblk, tb>>>(ei, n);
    k_count<<<eblk, tb>>>(ei, E);
    k_scanA<<<scblk, 1024>>>(n);
    k_scanB<<<1, 128>>>(scblk);
    k_scanC<<<scblk, 1024>>>(n, E);
    k_fill<<<eblk, tb>>>(ei, E);

    // layer 0
    k_gemm128h<false><<<gblk, 256>>>(x, W0, b0, pHh, pAGG, n);
    k_spmm128<<<wblk, tb>>>(pHh, pAGG, n);
    // layer 1 (ReLU fused into next GEMM's A-load)
    k_gemm128h<true><<<gblk, 256>>>(pAGG, W1, b1, pHh, pAGG, n);
    k_spmm128<<<wblk, tb>>>(pHh, pAGG, n);
    // layer 2 (tensor-core, relu fused; fp16 pre-scaled messages)
    k_gemm40h<<<gblk, 256>>>(pAGG, W2, b2, pH2h, out, n);
    k_spmm40h<<<wblk, tb>>>(pH2h, out, n);
}